// round 9
// baseline (speedup 1.0000x reference)
#include <cuda_runtime.h>
#include <cuda_bf16.h>
#include <math.h>

// ---------------- model constants ----------------
#define Vv 50257
#define VP 50304            // padded vocab (multiple of 128)
#define Dd 768
#define Hh 12
#define HD 64
#define Tt 1024
#define Ll 6
#define Bb 4
#define BT (Bb*Tt)          // 4096
#define FF (4*Dd)           // 3072

#define BM 128
#define BN 128
#define BKK 32
#define ATP 68              // attention smem row stride (floats)

// ---------------- scratch (static device arrays; no allocation) ----------------
__device__ float g_x   [BT*Dd];
__device__ float g_x2  [BT*Dd];
__device__ float g_q   [BT*Dd];
__device__ float g_k   [BT*Dd];
__device__ float g_v   [BT*Dd];
__device__ float g_y   [BT*Dd];
__device__ float g_ff1 [BT*FF];
__device__ float g_rl  [BT];
__device__ float g_wpad[(size_t)Dd*VP];   // padded, pre-tf32 head weights

__device__ __forceinline__ float to_tf32(float x) {
    float y;
    asm("cvt.rna.tf32.f32 %0, %1;" : "=f"(y) : "f"(x));
    return y;
}

// ---------------- embedding ----------------
__global__ void embed_kernel(const int* __restrict__ idx,
                             const float* __restrict__ tok,
                             const float* __restrict__ pos,
                             float* __restrict__ x) {
    int r = blockIdx.x;
    int t = r & (Tt - 1);
    int token = idx[r];
    const float* tr = tok + (size_t)token * Dd;
    const float* pr = pos + (size_t)t * Dd;
    float* xr = x + (size_t)r * Dd;
    for (int c = threadIdx.x; c < Dd; c += blockDim.x)
        xr[c] = tr[c] + pr[c];
}

// ---------------- pad + pre-convert head weights ----------------
__global__ void padw_kernel(const float* __restrict__ w, float* __restrict__ wp) {
    int kk = blockIdx.x;             // 0..767
    const float* src = w + (size_t)kk * Vv;
    float* dst = wp + (size_t)kk * VP;
    for (int n = threadIdx.x; n < VP; n += blockDim.x)
        dst[n] = (n < Vv) ? to_tf32(src[n]) : 0.f;
}

// ---------------- TF32 tensor-core GEMM core (R3 structure, BK=32) ----------------
// fill -> sync -> compute -> sync.  64 MMAs per barrier pair.
template<int EPI>
__device__ __forceinline__ void gemm_core(
    const float* __restrict__ A, const float* __restrict__ Bm,
    const float* __restrict__ bias, float* __restrict__ C,
    int N, int K, int Bstride, int row0, int col0)
{
    __shared__ float As[BKK][BM + 4];   // As[k][m]  ~16.9 KB
    __shared__ float Bs[BKK][BN + 4];   // Bs[k][n]  ~16.9 KB

    int t    = threadIdx.x;
    int wid  = t >> 5;
    int lane = t & 31;
    int g    = lane >> 2;
    int tig  = lane & 3;
    int m0w  = (wid & 1) * 64;
    int n0w  = (wid >> 1) * 32;

    const bool vec_ok = ((col0 + BN) <= Bstride) && ((Bstride & 3) == 0);

    float acc[4][4][4];
#pragma unroll
    for (int im = 0; im < 4; im++)
#pragma unroll
        for (int in = 0; in < 4; in++)
#pragma unroll
            for (int c = 0; c < 4; c++) acc[im][in][c] = 0.f;

    for (int k0 = 0; k0 < K; k0 += BKK) {
        // ---- load A tile: 128x32, 4 float4 per thread, transpose to As[k][m] ----
#pragma unroll
        for (int i = 0; i < 4; i++) {
            int idx = t + i * 256;          // 0..1023
            int row = idx >> 3;             // 0..127
            int seg = (idx & 7) * 4;        // 0,4,...,28
            float4 a4 = *(const float4*)(A + (size_t)(row0 + row) * K + k0 + seg);
            As[seg + 0][row] = to_tf32(a4.x);
            As[seg + 1][row] = to_tf32(a4.y);
            As[seg + 2][row] = to_tf32(a4.z);
            As[seg + 3][row] = to_tf32(a4.w);
        }
        // ---- load B tile: 32x128 ----
        if (vec_ok) {
#pragma unroll
            for (int i = 0; i < 4; i++) {
                int idx = t + i * 256;      // 0..1023
                int kr  = idx >> 5;         // 0..31
                int cs  = (idx & 31) * 4;   // 0..124
                float4 b4 = *(const float4*)(Bm + (size_t)(k0 + kr) * Bstride + col0 + cs);
                Bs[kr][cs + 0] = to_tf32(b4.x);
                Bs[kr][cs + 1] = to_tf32(b4.y);
                Bs[kr][cs + 2] = to_tf32(b4.z);
                Bs[kr][cs + 3] = to_tf32(b4.w);
            }
        } else {
#pragma unroll
            for (int i = 0; i < 16; i++) {
                int e = t + i * 256;        // 0..4095
                int kr = e >> 7;            // 0..31
                int c  = e & 127;
                int col = col0 + c;
                Bs[kr][c] = (col < Bstride) ? to_tf32(Bm[(size_t)(k0 + kr) * Bstride + col]) : 0.f;
            }
        }
        __syncthreads();

#pragma unroll
        for (int ks = 0; ks < BKK; ks += 8) {
            unsigned af[4][4], bf[4][2];
#pragma unroll
            for (int im = 0; im < 4; im++) {
                int m = m0w + im * 16 + g;
                af[im][0] = __float_as_uint(As[ks + tig    ][m    ]);
                af[im][1] = __float_as_uint(As[ks + tig    ][m + 8]);
                af[im][2] = __float_as_uint(As[ks + tig + 4][m    ]);
                af[im][3] = __float_as_uint(As[ks + tig + 4][m + 8]);
            }
#pragma unroll
            for (int in = 0; in < 4; in++) {
                int n = n0w + in * 8 + g;
                bf[in][0] = __float_as_uint(Bs[ks + tig    ][n]);
                bf[in][1] = __float_as_uint(Bs[ks + tig + 4][n]);
            }
#pragma unroll
            for (int im = 0; im < 4; im++)
#pragma unroll
                for (int in = 0; in < 4; in++) {
                    asm volatile(
                        "mma.sync.aligned.m16n8k8.row.col.f32.tf32.tf32.f32 "
                        "{%0,%1,%2,%3},{%4,%5,%6,%7},{%8,%9},{%0,%1,%2,%3};"
                        : "+f"(acc[im][in][0]), "+f"(acc[im][in][1]),
                          "+f"(acc[im][in][2]), "+f"(acc[im][in][3])
                        : "r"(af[im][0]), "r"(af[im][1]), "r"(af[im][2]), "r"(af[im][3]),
                          "r"(bf[in][0]), "r"(bf[in][1]));
                }
        }
        __syncthreads();
    }

#pragma unroll
    for (int im = 0; im < 4; im++) {
        int r_lo = row0 + m0w + im * 16 + g;
        int r_hi = r_lo + 8;
#pragma unroll
        for (int in = 0; in < 4; in++) {
            int c_lo = col0 + n0w + in * 8 + 2 * tig;
            int c_hi = c_lo + 1;
            float v0 = acc[im][in][0], v1 = acc[im][in][1];
            float v2 = acc[im][in][2], v3 = acc[im][in][3];
            if (EPI >= 1) {
                if (c_lo < N) { v0 += bias[c_lo]; v2 += bias[c_lo]; }
                if (c_hi < N) { v1 += bias[c_hi]; v3 += bias[c_hi]; }
            }
            if (EPI == 2) {
                v0 = fmaxf(v0, 0.f); v1 = fmaxf(v1, 0.f);
                v2 = fmaxf(v2, 0.f); v3 = fmaxf(v3, 0.f);
            }
            size_t blo = (size_t)r_lo * N;
            size_t bhi = (size_t)r_hi * N;
            if (c_lo < N) { C[blo + c_lo] = v0; C[bhi + c_lo] = v2; }
            if (c_hi < N) { C[blo + c_hi] = v1; C[bhi + c_hi] = v3; }
        }
    }
}

template<int EPI>
__global__ __launch_bounds__(256)
void tgemm_kernel(const float* __restrict__ A, const float* __restrict__ Bm,
                  const float* __restrict__ bias, float* __restrict__ C,
                  int N, int K, int Bstride) {
    gemm_core<EPI>(A, Bm, bias, C, N, K, Bstride,
                   blockIdx.y * BM, blockIdx.x * BN);
}

__global__ __launch_bounds__(256)
void qkv_kernel(const float* __restrict__ x,
                const float* __restrict__ wq, const float* __restrict__ wk,
                const float* __restrict__ wv,
                float* __restrict__ q, float* __restrict__ k, float* __restrict__ v) {
    int ct  = blockIdx.x;
    int mat = ct / 6;
    int c   = ct % 6;
    const float* B = (mat == 0) ? wq : (mat == 1) ? wk : wv;
    float*       C = (mat == 0) ? q  : (mat == 1) ? k  : v;
    gemm_core<0>(x, B, nullptr, C, Dd, Dd, Dd, blockIdx.y * BM, c * BN);
}

// ---------------- tensor-core causal flash attention (R8-verified, FROZEN) ----------------
#define ATTN_SMEM ((4*64*ATP + 64*3 + 2*64*2) * 4)
__global__ __launch_bounds__(256)
void attn_kernel(const float* __restrict__ q, const float* __restrict__ k,
                 const float* __restrict__ v, float* __restrict__ y) {
    extern __shared__ float asmem[];
    float* Qs   = asmem;               // [64][ATP]
    float* Ks   = Qs + 64 * ATP;
    float* Vs   = Ks + 64 * ATP;
    float* Ps   = Vs + 64 * ATP;
    float* mrow = Ps + 64 * ATP;
    float* lrow = mrow + 64;
    float* cfac = lrow + 64;
    float* pmax = cfac + 64;           // [2][64]
    float* psum = pmax + 128;          // [2][64]

    int t    = threadIdx.x;
    int wid  = t >> 5;
    int lane = t & 31;
    int g    = lane >> 2;
    int tig  = lane & 3;
    int m0   = (wid & 3) * 16;
    int n0   = (wid >> 2) * 32;
    int nch  = wid >> 2;

    int q0 = blockIdx.x * 64;
    int h  = blockIdx.y;
    int b  = blockIdx.z;

    for (int i = t; i < 64 * 16; i += 256) {
        int r = i >> 4, c4 = i & 15;
        float4 qv = *(const float4*)(q + ((size_t)(b * Tt + q0 + r)) * Dd + h * HD + c4 * 4);
        float* d = Qs + r * ATP + c4 * 4;
        d[0] = to_tf32(qv.x); d[1] = to_tf32(qv.y);
        d[2] = to_tf32(qv.z); d[3] = to_tf32(qv.w);
    }
    if (t < 64) { mrow[t] = -1e30f; lrow[t] = 0.f; }

    float oacc[4][4];
#pragma unroll
    for (int in = 0; in < 4; in++)
#pragma unroll
        for (int c = 0; c < 4; c++) oacc[in][c] = 0.f;

    int ntiles = blockIdx.x + 1;
    __syncthreads();

    for (int jt = 0; jt < ntiles; jt++) {
        int s0 = jt * 64;
        bool diag = (jt == ntiles - 1);

        for (int i = t; i < 64 * 16; i += 256) {
            int r = i >> 4, c4 = i & 15;
            size_t gb = ((size_t)(b * Tt + s0 + r)) * Dd + h * HD + c4 * 4;
            float4 kv = *(const float4*)(k + gb);
            float4 vv = *(const float4*)(v + gb);
            float* dk = Ks + r * ATP + c4 * 4;
            dk[0] = to_tf32(kv.x); dk[1] = to_tf32(kv.y);
            dk[2] = to_tf32(kv.z); dk[3] = to_tf32(kv.w);
            float* dv = Vs + r * ATP + c4 * 4;
            dv[0] = to_tf32(vv.x); dv[1] = to_tf32(vv.y);
            dv[2] = to_tf32(vv.z); dv[3] = to_tf32(vv.w);
        }
        __syncthreads();

        float sacc[4][4];
#pragma unroll
        for (int in = 0; in < 4; in++)
#pragma unroll
            for (int c = 0; c < 4; c++) sacc[in][c] = 0.f;
#pragma unroll
        for (int k8 = 0; k8 < 8; k8++) {
            int kk = k8 * 8;
            unsigned a0 = __float_as_uint(Qs[(m0 + g    ) * ATP + kk + tig    ]);
            unsigned a1 = __float_as_uint(Qs[(m0 + g + 8) * ATP + kk + tig    ]);
            unsigned a2 = __float_as_uint(Qs[(m0 + g    ) * ATP + kk + tig + 4]);
            unsigned a3 = __float_as_uint(Qs[(m0 + g + 8) * ATP + kk + tig + 4]);
#pragma unroll
            for (int in = 0; in < 4; in++) {
                unsigned b0 = __float_as_uint(Ks[(n0 + in * 8 + g) * ATP + kk + tig    ]);
                unsigned b1 = __float_as_uint(Ks[(n0 + in * 8 + g) * ATP + kk + tig + 4]);
                asm volatile(
                    "mma.sync.aligned.m16n8k8.row.col.f32.tf32.tf32.f32 "
                    "{%0,%1,%2,%3},{%4,%5,%6,%7},{%8,%9},{%0,%1,%2,%3};"
                    : "+f"(sacc[in][0]), "+f"(sacc[in][1]),
                      "+f"(sacc[in][2]), "+f"(sacc[in][3])
                    : "r"(a0), "r"(a1), "r"(a2), "r"(a3), "r"(b0), "r"(b1));
            }
        }

        int r0 = m0 + g, r1 = m0 + g + 8;
#pragma unroll
        for (int in = 0; in < 4; in++) {
            int c0 = n0 + in * 8 + 2 * tig, c1 = c0 + 1;
            sacc[in][0] *= 0.125f; sacc[in][1] *= 0.125f;
            sacc[in][2] *= 0.125f; sacc[in][3] *= 0.125f;
            if (diag) {
                if (c0 > r0) sacc[in][0] = -1e30f;
                if (c1 > r0) sacc[in][1] = -1e30f;
                if (c0 > r1) sacc[in][2] = -1e30f;
                if (c1 > r1) sacc[in][3] = -1e30f;
            }
        }

        float rmax0 = -1e30f, rmax1 = -1e30f;
#pragma unroll
        for (int in = 0; in < 4; in++) {
            rmax0 = fmaxf(rmax0, fmaxf(sacc[in][0], sacc[in][1]));
            rmax1 = fmaxf(rmax1, fmaxf(sacc[in][2], sacc[in][3]));
        }
        rmax0 = fmaxf(rmax0, __shfl_xor_sync(0xffffffffu, rmax0, 1));
        rmax0 = fmaxf(rmax0, __shfl_xor_sync(0xffffffffu, rmax0, 2));
        rmax1 = fmaxf(rmax1, __shfl_xor_sync(0xffffffffu, rmax1, 1));
        rmax1 = fmaxf(rmax1, __shfl_xor_sync(0xffffffffu, rmax1, 2));
        if (tig == 0) {
            pmax[nch * 64 + r0] = rmax0;
            pmax[nch * 64 + r1] = rmax1;
        }
        __syncthreads();

        if (t < 64) {
            float nm = fmaxf(mrow[t], fmaxf(pmax[t], pmax[64 + t]));
            cfac[t] = __expf(mrow[t] - nm);
            mrow[t] = nm;
        }
        __syncthreads();

        float nm0 = mrow[r0], nm1 = mrow[r1];
        float rs0 = 0.f, rs1 = 0.f;
#pragma unroll
        for (int in = 0; in < 4; in++) {
            int c0 = n0 + in * 8 + 2 * tig;
            float p0 = __expf(sacc[in][0] - nm0);
            float p1 = __expf(sacc[in][1] - nm0);
            float p2 = __expf(sacc[in][2] - nm1);
            float p3 = __expf(sacc[in][3] - nm1);
            rs0 += p0 + p1; rs1 += p2 + p3;
            Ps[r0 * ATP + c0    ] = to_tf32(p0);
            Ps[r0 * ATP + c0 + 1] = to_tf32(p1);
            Ps[r1 * ATP + c0    ] = to_tf32(p2);
            Ps[r1 * ATP + c0 + 1] = to_tf32(p3);
        }
        rs0 += __shfl_xor_sync(0xffffffffu, rs0, 1);
        rs0 += __shfl_xor_sync(0xffffffffu, rs0, 2);
        rs1 += __shfl_xor_sync(0xffffffffu, rs1, 1);
        rs1 += __shfl_xor_sync(0xffffffffu, rs1, 2);
        if (tig == 0) {
            psum[nch * 64 + r0] = rs0;
            psum[nch * 64 + r1] = rs1;
        }
        __syncthreads();

        if (t < 64) lrow[t] = lrow[t] * cfac[t] + psum[t] + psum[64 + t];

        float corr0 = cfac[r0], corr1 = cfac[r1];
#pragma unroll
        for (int in = 0; in < 4; in++) {
            oacc[in][0] *= corr0; oacc[in][1] *= corr0;
            oacc[in][2] *= corr1; oacc[in][3] *= corr1;
        }

#pragma unroll
        for (int k8 = 0; k8 < 8; k8++) {
            int kk = k8 * 8;
            unsigned a0 = __float_as_uint(Ps[(m0 + g    ) * ATP + kk + tig    ]);
            unsigned a1 = __float_as_uint(Ps[(m0 + g + 8) * ATP + kk + tig    ]);
            unsigned a2 = __float_as_uint(Ps[(m0 + g    ) * ATP + kk + tig + 4]);
            unsigned a3 = __float_as_uint(Ps[(m0 + g + 8) * ATP + kk + tig + 4]);
#pragma unroll
            for (int in = 0; in < 4; in++) {
                unsigned b0 = __float_as_uint(Vs[(kk + tig    ) * ATP + n0 + in * 8 + g]);
                unsigned b1 = __float_as_uint(Vs[(kk + tig + 4) * ATP + n0 + in * 8 + g]);
                asm volatile(
                    "mma.sync.aligned.m16n8k8.row.col.f32.tf32.tf32.f32 "
                    "{%0,%1,%2,%3},{%4,%5,%6,%7},{%8,%9},{%0,%1,%2,%3};"
                    : "+f"(oacc[in][0]), "+f"(oacc[in][1]),
                      "+f"(oacc[in][2]), "+f"(oacc[in][3])
                    : "r"(a0), "r"(a1), "r"(a2), "r"(a3), "r"(b0), "r"(b1));
            }
        }
        __syncthreads();
    }

    int r0 = m0 + g, r1 = m0 + g + 8;
    float inv0 = 1.f / lrow[r0];
    float inv1 = 1.f / lrow[r1];
#pragma unroll
    for (int in = 0; in < 4; in++) {
        int c0 = n0 + in * 8 + 2 * tig;
        float2 o0, o1;
        o0.x = oacc[in][0] * inv0; o0.y = oacc[in][1] * inv0;
        o1.x = oacc[in][2] * inv1; o1.y = oacc[in][3] * inv1;
        *(float2*)(y + ((size_t)(b * Tt + q0 + r0)) * Dd + h * HD + c0) = o0;
        *(float2*)(y + ((size_t)(b * Tt + q0 + r1)) * Dd + h * HD + c0) = o1;
    }
}

// ---------------- residual + LayerNorm ----------------
__global__ __launch_bounds__(256)
void ln_res_kernel(const float* __restrict__ a, const float* __restrict__ b,
                   const float* __restrict__ g, const float* __restrict__ be,
                   float* __restrict__ out) {
    __shared__ float buf[Dd];
    __shared__ float red[256];
    int r = blockIdx.x;
    int t = threadIdx.x;
    const float* ar = a + (size_t)r * Dd;
    const float* br = b + (size_t)r * Dd;

    float s = 0.f;
    for (int c = t; c < Dd; c += 256) {
        float vv = ar[c] + br[c];
        buf[c] = vv;
        s += vv;
    }
    red[t] = s; __syncthreads();
    for (int o = 128; o > 0; o >>= 1) { if (t < o) red[t] += red[t + o]; __syncthreads(); }
    float mu = red[0] / (float)Dd;
    __syncthreads();

    float s2 = 0.f;
    for (int c = t; c < Dd; c += 256) {
        float d = buf[c] - mu;
        s2 += d * d;
    }
    red[t] = s2; __syncthreads();
    for (int o = 128; o > 0; o >>= 1) { if (t < o) red[t] += red[t + o]; __syncthreads(); }
    float rstd = rsqrtf(red[0] / (float)Dd + 1e-5f);

    float* orr = out + (size_t)r * Dd;
    for (int c = t; c < Dd; c += 256)
        orr[c] = (buf[c] - mu) * rstd * g[c] + be[c];
}

// ---------------- per-row cross-entropy ----------------
__global__ __launch_bounds__(256)
void rowloss_kernel(const float* __restrict__ logits, const int* __restrict__ tgt,
                    float* __restrict__ rl) {
    __shared__ float sm[256], sl[256];
    int r = blockIdx.x;
    int t = threadIdx.x;
    const float* lg = logits + (size_t)r * Vv;

    float m = -1e30f, l = 0.f;
    for (int c = t; c < Vv; c += 256) {
        float x = lg[c];
        if (x > m) { l = l * __expf(m - x) + 1.f; m = x; }
        else       { l += __expf(x - m); }
    }
    sm[t] = m; sl[t] = l; __syncthreads();
    for (int o = 128; o > 0; o >>= 1) {
        if (t < o) {
            float m1 = sm[t], m2 = sm[t + o];
            float M = fmaxf(m1, m2);
            sl[t] = sl[t] * __expf(m1 - M) + sl[t + o] * __expf(m2 - M);
            sm[t] = M;
        }
        __syncthreads();
    }
    if (t == 0)
        rl[r] = (sm[0] + logf(sl[0])) - lg[tgt[r]];
}

__global__ __launch_bounds__(256)
void meanloss_kernel(const float* __restrict__ rl, float* __restrict__ out) {
    __shared__ float red[256];
    int t = threadIdx.x;
    float s = 0.f;
    for (int i = t; i < BT; i += 256) s += rl[i];
    red[t] = s; __syncthreads();
    for (int o = 128; o > 0; o >>= 1) { if (t < o) red[t] += red[t + o]; __syncthreads(); }
    if (t == 0) out[0] = red[0] / (float)BT;
}

// ---------------- launch ----------------
extern "C" void kernel_launch(void* const* d_in, const int* in_sizes, int n_in,
                              void* d_out, int out_size) {
    const int*   idx    = (const int*)  d_in[0];
    const int*   tgt    = (const int*)  d_in[1];
    const float* tok    = (const float*)d_in[2];
    const float* pos    = (const float*)d_in[3];
    const float* Wq     = (const float*)d_in[4];
    const float* Wk     = (const float*)d_in[5];
    const float* Wv     = (const float*)d_in[6];
    const float* ln1g   = (const float*)d_in[7];
    const float* ln1b   = (const float*)d_in[8];
    const float* W1     = (const float*)d_in[9];
    const float* b1     = (const float*)d_in[10];
    const float* W2     = (const float*)d_in[11];
    const float* b2     = (const float*)d_in[12];
    const float* ln2g   = (const float*)d_in[13];
    const float* ln2b   = (const float*)d_in[14];
    const float* headw  = (const float*)d_in[15];
    const float* headb  = (const float*)d_in[16];
    float* out = (float*)d_out;

    float *x, *x2, *q, *k, *v, *y, *ff1, *rl, *wpad;
    cudaGetSymbolAddress((void**)&x,    g_x);
    cudaGetSymbolAddress((void**)&x2,   g_x2);
    cudaGetSymbolAddress((void**)&q,    g_q);
    cudaGetSymbolAddress((void**)&k,    g_k);
    cudaGetSymbolAddress((void**)&v,    g_v);
    cudaGetSymbolAddress((void**)&y,    g_y);
    cudaGetSymbolAddress((void**)&ff1,  g_ff1);
    cudaGetSymbolAddress((void**)&rl,   g_rl);
    cudaGetSymbolAddress((void**)&wpad, g_wpad);

    cudaFuncSetAttribute(attn_kernel,
                         cudaFuncAttributeMaxDynamicSharedMemorySize, ATTN_SMEM);

    embed_kernel<<<BT, 256>>>(idx, tok, pos, x);
    padw_kernel<<<Dd, 256>>>(headw, wpad);

    dim3 gQKV(18, BT / 128);
    dim3 gD(Dd / 128, BT / 128);             // 6 x 32
    dim3 gF(FF / 128, BT / 128);             // 24 x 32
    dim3 gV(VP / 128, BT / 128);             // 393 x 32

    for (int l = 0; l < Ll; l++) {
        const float* wq = Wq + (size_t)l * Dd * Dd;
        const float* wk = Wk + (size_t)l * Dd * Dd;
        const float* wv = Wv + (size_t)l * Dd * Dd;
        const float* w1 = W1 + (size_t)l * Dd * FF;
        const float* w2 = W2 + (size_t)l * FF * Dd;

        qkv_kernel<<<gQKV, 256>>>(x, wq, wk, wv, q, k, v);

        attn_kernel<<<dim3(Tt / 64, Hh, Bb), 256, ATTN_SMEM>>>(q, k, v, y);

        ln_res_kernel<<<BT, 256>>>(y, x, ln1g + l * Dd, ln1b + l * Dd, x2);

        tgemm_kernel<2><<<gF, 256>>>(x2, w1, b1 + (size_t)l * FF, ff1, FF, Dd, FF);
        tgemm_kernel<1><<<gD, 256>>>(ff1, w2, b2 + (size_t)l * Dd, y, Dd, FF, Dd);

        ln_res_kernel<<<BT, 256>>>(y, x2, ln2g + l * Dd, ln2b + l * Dd, x);
    }

    tgemm_kernel<1><<<gV, 256>>>(x, wpad, headb, out, Vv, Dd, VP);

    rowloss_kernel<<<BT, 256>>>(out, tgt, rl);
    meanloss_kernel<<<1, 256>>>(rl, out + (size_t)BT * Vv);
}

// round 11
// speedup vs baseline: 1.4352x; 1.4352x over previous
#include <cuda_runtime.h>
#include <cuda_bf16.h>
#include <math.h>

// ---------------- model constants ----------------
#define Vv 50257
#define VP 50304            // padded vocab (multiple of 128)
#define Dd 768
#define Hh 12
#define HD 64
#define Tt 1024
#define Ll 6
#define Bb 4
#define BT (Bb*Tt)          // 4096
#define FF (4*Dd)           // 3072

#define BM 128
#define BN 128
#define BKK 16
#define ATP 68              // attention smem row stride (floats)
#define KSPL 1024           // FFN2 split-K chunk (3 parts of 3072)

// ---------------- scratch (static device arrays; no allocation) ----------------
__device__ float g_x   [BT*Dd];
__device__ float g_x2  [BT*Dd];
__device__ float g_q   [BT*Dd];
__device__ float g_k   [BT*Dd];
__device__ float g_v   [BT*Dd];
__device__ float g_y   [BT*Dd];
__device__ float g_ff1 [BT*FF];
__device__ float g_rl  [BT];
__device__ float g_wpad[(size_t)Dd*VP];   // padded, pre-tf32 head weights

__device__ __forceinline__ float to_tf32(float x) {
    float y;
    asm("cvt.rna.tf32.f32 %0, %1;" : "=f"(y) : "f"(x));
    return y;
}

// ---------------- embedding ----------------
__global__ void embed_kernel(const int* __restrict__ idx,
                             const float* __restrict__ tok,
                             const float* __restrict__ pos,
                             float* __restrict__ x) {
    int r = blockIdx.x;
    int t = r & (Tt - 1);
    int token = idx[r];
    const float* tr = tok + (size_t)token * Dd;
    const float* pr = pos + (size_t)t * Dd;
    float* xr = x + (size_t)r * Dd;
    for (int c = threadIdx.x; c < Dd; c += blockDim.x)
        xr[c] = tr[c] + pr[c];
}

// ---------------- pad + pre-convert head weights ----------------
__global__ void padw_kernel(const float* __restrict__ w, float* __restrict__ wp) {
    int kk = blockIdx.x;             // 0..767
    const float* src = w + (size_t)kk * Vv;
    float* dst = wp + (size_t)kk * VP;
    for (int n = threadIdx.x; n < VP; n += blockDim.x)
        dst[n] = (n < Vv) ? to_tf32(src[n]) : 0.f;
}

// ---------------- TF32 tensor-core GEMM core (R3 mainloop, FROZEN; Astride added) ----------------
template<int EPI>
__device__ __forceinline__ void gemm_core(
    const float* __restrict__ A, const float* __restrict__ Bm,
    const float* __restrict__ bias, float* __restrict__ C,
    int N, int K, int Astride, int Bstride, int row0, int col0)
{
    __shared__ float As[BKK][BM + 4];   // As[k][m]
    __shared__ float Bs[BKK][BN + 4];   // Bs[k][n]

    int t    = threadIdx.x;
    int wid  = t >> 5;
    int lane = t & 31;
    int g    = lane >> 2;
    int tig  = lane & 3;
    int m0w  = (wid & 1) * 64;
    int n0w  = (wid >> 1) * 32;

    const bool vec_ok = ((col0 + BN) <= Bstride) && ((Bstride & 3) == 0);

    float acc[4][4][4];
#pragma unroll
    for (int im = 0; im < 4; im++)
#pragma unroll
        for (int in = 0; in < 4; in++)
#pragma unroll
            for (int c = 0; c < 4; c++) acc[im][in][c] = 0.f;

    for (int k0 = 0; k0 < K; k0 += BKK) {
#pragma unroll
        for (int i = 0; i < 2; i++) {
            int idx = t + i * 256;
            int row = idx >> 2;
            int seg = (idx & 3) * 4;
            float4 a4 = *(const float4*)(A + (size_t)(row0 + row) * Astride + k0 + seg);
            As[seg + 0][row] = to_tf32(a4.x);
            As[seg + 1][row] = to_tf32(a4.y);
            As[seg + 2][row] = to_tf32(a4.z);
            As[seg + 3][row] = to_tf32(a4.w);
        }
        if (vec_ok) {
#pragma unroll
            for (int i = 0; i < 2; i++) {
                int idx = t + i * 256;
                int kr  = idx >> 5;
                int cs  = (idx & 31) * 4;
                float4 b4 = *(const float4*)(Bm + (size_t)(k0 + kr) * Bstride + col0 + cs);
                Bs[kr][cs + 0] = to_tf32(b4.x);
                Bs[kr][cs + 1] = to_tf32(b4.y);
                Bs[kr][cs + 2] = to_tf32(b4.z);
                Bs[kr][cs + 3] = to_tf32(b4.w);
            }
        } else {
#pragma unroll
            for (int i = 0; i < 8; i++) {
                int e = t + i * 256;
                int kr = e >> 7;
                int c  = e & 127;
                int col = col0 + c;
                Bs[kr][c] = (col < Bstride) ? to_tf32(Bm[(size_t)(k0 + kr) * Bstride + col]) : 0.f;
            }
        }
        __syncthreads();

#pragma unroll
        for (int ks = 0; ks < BKK; ks += 8) {
            unsigned af[4][4], bf[4][2];
#pragma unroll
            for (int im = 0; im < 4; im++) {
                int m = m0w + im * 16 + g;
                af[im][0] = __float_as_uint(As[ks + tig    ][m    ]);
                af[im][1] = __float_as_uint(As[ks + tig    ][m + 8]);
                af[im][2] = __float_as_uint(As[ks + tig + 4][m    ]);
                af[im][3] = __float_as_uint(As[ks + tig + 4][m + 8]);
            }
#pragma unroll
            for (int in = 0; in < 4; in++) {
                int n = n0w + in * 8 + g;
                bf[in][0] = __float_as_uint(Bs[ks + tig    ][n]);
                bf[in][1] = __float_as_uint(Bs[ks + tig + 4][n]);
            }
#pragma unroll
            for (int im = 0; im < 4; im++)
#pragma unroll
                for (int in = 0; in < 4; in++) {
                    asm volatile(
                        "mma.sync.aligned.m16n8k8.row.col.f32.tf32.tf32.f32 "
                        "{%0,%1,%2,%3},{%4,%5,%6,%7},{%8,%9},{%0,%1,%2,%3};"
                        : "+f"(acc[im][in][0]), "+f"(acc[im][in][1]),
                          "+f"(acc[im][in][2]), "+f"(acc[im][in][3])
                        : "r"(af[im][0]), "r"(af[im][1]), "r"(af[im][2]), "r"(af[im][3]),
                          "r"(bf[in][0]), "r"(bf[in][1]));
                }
        }
        __syncthreads();
    }

#pragma unroll
    for (int im = 0; im < 4; im++) {
        int r_lo = row0 + m0w + im * 16 + g;
        int r_hi = r_lo + 8;
#pragma unroll
        for (int in = 0; in < 4; in++) {
            int c_lo = col0 + n0w + in * 8 + 2 * tig;
            int c_hi = c_lo + 1;
            float v0 = acc[im][in][0], v1 = acc[im][in][1];
            float v2 = acc[im][in][2], v3 = acc[im][in][3];
            if (EPI >= 1) {
                if (c_lo < N) { v0 += bias[c_lo]; v2 += bias[c_lo]; }
                if (c_hi < N) { v1 += bias[c_hi]; v3 += bias[c_hi]; }
            }
            if (EPI == 2) {
                v0 = fmaxf(v0, 0.f); v1 = fmaxf(v1, 0.f);
                v2 = fmaxf(v2, 0.f); v3 = fmaxf(v3, 0.f);
            }
            size_t blo = (size_t)r_lo * N;
            size_t bhi = (size_t)r_hi * N;
            if (c_lo < N) { C[blo + c_lo] = v0; C[bhi + c_lo] = v2; }
            if (c_hi < N) { C[blo + c_hi] = v1; C[bhi + c_hi] = v3; }
        }
    }
}

template<int EPI>
__global__ __launch_bounds__(256)
void tgemm_kernel(const float* __restrict__ A, const float* __restrict__ Bm,
                  const float* __restrict__ bias, float* __restrict__ C,
                  int N, int K, int Bstride) {
    gemm_core<EPI>(A, Bm, bias, C, N, K, K, Bstride,
                   blockIdx.y * BM, blockIdx.x * BN);
}

// fused QKV: grid (18, 32); blockIdx.x selects {Wq,Wk,Wv} x 6 col-tiles
__global__ __launch_bounds__(256)
void qkv_kernel(const float* __restrict__ x,
                const float* __restrict__ wq, const float* __restrict__ wk,
                const float* __restrict__ wv,
                float* __restrict__ q, float* __restrict__ k, float* __restrict__ v) {
    int ct  = blockIdx.x;
    int mat = ct / 6;
    int c   = ct % 6;
    const float* B = (mat == 0) ? wq : (mat == 1) ? wk : wv;
    float*       C = (mat == 0) ? q  : (mat == 1) ? k  : v;
    gemm_core<0>(x, B, nullptr, C, Dd, Dd, Dd, Dd, blockIdx.y * BM, c * BN);
}

// fused split-K FFN2: grid (18, 32); blockIdx.x = part(3) x col-tile(6).
// part p computes A[:, p*1024:(p+1)*1024] @ W2[p*1024:(p+1)*1024, :] -> y_p.
// Bias folded into part 0. Partials summed (fixed order) inside ln_res4.
__global__ __launch_bounds__(256)
void ffn2_kernel(const float* __restrict__ ff1, const float* __restrict__ w2,
                 const float* __restrict__ bias,
                 float* __restrict__ y0, float* __restrict__ y1, float* __restrict__ y2) {
    int p = blockIdx.x / 6;
    int c = blockIdx.x % 6;
    const float* A = ff1 + p * KSPL;
    const float* B = w2 + (size_t)p * KSPL * Dd;
    int row0 = blockIdx.y * BM, col0 = c * BN;
    if (p == 0)      gemm_core<1>(A, B, bias,    y0, Dd, KSPL, FF, Dd, row0, col0);
    else if (p == 1) gemm_core<0>(A, B, nullptr, y1, Dd, KSPL, FF, Dd, row0, col0);
    else             gemm_core<0>(A, B, nullptr, y2, Dd, KSPL, FF, Dd, row0, col0);
}

// ---------------- tensor-core causal flash attention (R8-verified, FROZEN) ----------------
#define ATTN_SMEM ((4*64*ATP + 64*3 + 2*64*2) * 4)
__global__ __launch_bounds__(256)
void attn_kernel(const float* __restrict__ q, const float* __restrict__ k,
                 const float* __restrict__ v, float* __restrict__ y) {
    extern __shared__ float asmem[];
    float* Qs   = asmem;               // [64][ATP]
    float* Ks   = Qs + 64 * ATP;
    float* Vs   = Ks + 64 * ATP;
    float* Ps   = Vs + 64 * ATP;
    float* mrow = Ps + 64 * ATP;
    float* lrow = mrow + 64;
    float* cfac = lrow + 64;
    float* pmax = cfac + 64;           // [2][64]
    float* psum = pmax + 128;          // [2][64]

    int t    = threadIdx.x;
    int wid  = t >> 5;
    int lane = t & 31;
    int g    = lane >> 2;
    int tig  = lane & 3;
    int m0   = (wid & 3) * 16;
    int n0   = (wid >> 2) * 32;
    int nch  = wid >> 2;

    int q0 = blockIdx.x * 64;
    int h  = blockIdx.y;
    int b  = blockIdx.z;

    for (int i = t; i < 64 * 16; i += 256) {
        int r = i >> 4, c4 = i & 15;
        float4 qv = *(const float4*)(q + ((size_t)(b * Tt + q0 + r)) * Dd + h * HD + c4 * 4);
        float* d = Qs + r * ATP + c4 * 4;
        d[0] = to_tf32(qv.x); d[1] = to_tf32(qv.y);
        d[2] = to_tf32(qv.z); d[3] = to_tf32(qv.w);
    }
    if (t < 64) { mrow[t] = -1e30f; lrow[t] = 0.f; }

    float oacc[4][4];
#pragma unroll
    for (int in = 0; in < 4; in++)
#pragma unroll
        for (int c = 0; c < 4; c++) oacc[in][c] = 0.f;

    int ntiles = blockIdx.x + 1;
    __syncthreads();

    for (int jt = 0; jt < ntiles; jt++) {
        int s0 = jt * 64;
        bool diag = (jt == ntiles - 1);

        for (int i = t; i < 64 * 16; i += 256) {
            int r = i >> 4, c4 = i & 15;
            size_t gb = ((size_t)(b * Tt + s0 + r)) * Dd + h * HD + c4 * 4;
            float4 kv = *(const float4*)(k + gb);
            float4 vv = *(const float4*)(v + gb);
            float* dk = Ks + r * ATP + c4 * 4;
            dk[0] = to_tf32(kv.x); dk[1] = to_tf32(kv.y);
            dk[2] = to_tf32(kv.z); dk[3] = to_tf32(kv.w);
            float* dv = Vs + r * ATP + c4 * 4;
            dv[0] = to_tf32(vv.x); dv[1] = to_tf32(vv.y);
            dv[2] = to_tf32(vv.z); dv[3] = to_tf32(vv.w);
        }
        __syncthreads();

        float sacc[4][4];
#pragma unroll
        for (int in = 0; in < 4; in++)
#pragma unroll
            for (int c = 0; c < 4; c++) sacc[in][c] = 0.f;
#pragma unroll
        for (int k8 = 0; k8 < 8; k8++) {
            int kk = k8 * 8;
            unsigned a0 = __float_as_uint(Qs[(m0 + g    ) * ATP + kk + tig    ]);
            unsigned a1 = __float_as_uint(Qs[(m0 + g + 8) * ATP + kk + tig    ]);
            unsigned a2 = __float_as_uint(Qs[(m0 + g    ) * ATP + kk + tig + 4]);
            unsigned a3 = __float_as_uint(Qs[(m0 + g + 8) * ATP + kk + tig + 4]);
#pragma unroll
            for (int in = 0; in < 4; in++) {
                unsigned b0 = __float_as_uint(Ks[(n0 + in * 8 + g) * ATP + kk + tig    ]);
                unsigned b1 = __float_as_uint(Ks[(n0 + in * 8 + g) * ATP + kk + tig + 4]);
                asm volatile(
                    "mma.sync.aligned.m16n8k8.row.col.f32.tf32.tf32.f32 "
                    "{%0,%1,%2,%3},{%4,%5,%6,%7},{%8,%9},{%0,%1,%2,%3};"
                    : "+f"(sacc[in][0]), "+f"(sacc[in][1]),
                      "+f"(sacc[in][2]), "+f"(sacc[in][3])
                    : "r"(a0), "r"(a1), "r"(a2), "r"(a3), "r"(b0), "r"(b1));
            }
        }

        int r0 = m0 + g, r1 = m0 + g + 8;
#pragma unroll
        for (int in = 0; in < 4; in++) {
            int c0 = n0 + in * 8 + 2 * tig, c1 = c0 + 1;
            sacc[in][0] *= 0.125f; sacc[in][1] *= 0.125f;
            sacc[in][2] *= 0.125f; sacc[in][3] *= 0.125f;
            if (diag) {
                if (c0 > r0) sacc[in][0] = -1e30f;
                if (c1 > r0) sacc[in][1] = -1e30f;
                if (c0 > r1) sacc[in][2] = -1e30f;
                if (c1 > r1) sacc[in][3] = -1e30f;
            }
        }

        float rmax0 = -1e30f, rmax1 = -1e30f;
#pragma unroll
        for (int in = 0; in < 4; in++) {
            rmax0 = fmaxf(rmax0, fmaxf(sacc[in][0], sacc[in][1]));
            rmax1 = fmaxf(rmax1, fmaxf(sacc[in][2], sacc[in][3]));
        }
        rmax0 = fmaxf(rmax0, __shfl_xor_sync(0xffffffffu, rmax0, 1));
        rmax0 = fmaxf(rmax0, __shfl_xor_sync(0xffffffffu, rmax0, 2));
        rmax1 = fmaxf(rmax1, __shfl_xor_sync(0xffffffffu, rmax1, 1));
        rmax1 = fmaxf(rmax1, __shfl_xor_sync(0xffffffffu, rmax1, 2));
        if (tig == 0) {
            pmax[nch * 64 + r0] = rmax0;
            pmax[nch * 64 + r1] = rmax1;
        }
        __syncthreads();

        if (t < 64) {
            float nm = fmaxf(mrow[t], fmaxf(pmax[t], pmax[64 + t]));
            cfac[t] = __expf(mrow[t] - nm);
            mrow[t] = nm;
        }
        __syncthreads();

        float nm0 = mrow[r0], nm1 = mrow[r1];
        float rs0 = 0.f, rs1 = 0.f;
#pragma unroll
        for (int in = 0; in < 4; in++) {
            int c0 = n0 + in * 8 + 2 * tig;
            float p0 = __expf(sacc[in][0] - nm0);
            float p1 = __expf(sacc[in][1] - nm0);
            float p2 = __expf(sacc[in][2] - nm1);
            float p3 = __expf(sacc[in][3] - nm1);
            rs0 += p0 + p1; rs1 += p2 + p3;
            Ps[r0 * ATP + c0    ] = to_tf32(p0);
            Ps[r0 * ATP + c0 + 1] = to_tf32(p1);
            Ps[r1 * ATP + c0    ] = to_tf32(p2);
            Ps[r1 * ATP + c0 + 1] = to_tf32(p3);
        }
        rs0 += __shfl_xor_sync(0xffffffffu, rs0, 1);
        rs0 += __shfl_xor_sync(0xffffffffu, rs0, 2);
        rs1 += __shfl_xor_sync(0xffffffffu, rs1, 1);
        rs1 += __shfl_xor_sync(0xffffffffu, rs1, 2);
        if (tig == 0) {
            psum[nch * 64 + r0] = rs0;
            psum[nch * 64 + r1] = rs1;
        }
        __syncthreads();

        if (t < 64) lrow[t] = lrow[t] * cfac[t] + psum[t] + psum[64 + t];

        float corr0 = cfac[r0], corr1 = cfac[r1];
#pragma unroll
        for (int in = 0; in < 4; in++) {
            oacc[in][0] *= corr0; oacc[in][1] *= corr0;
            oacc[in][2] *= corr1; oacc[in][3] *= corr1;
        }

#pragma unroll
        for (int k8 = 0; k8 < 8; k8++) {
            int kk = k8 * 8;
            unsigned a0 = __float_as_uint(Ps[(m0 + g    ) * ATP + kk + tig    ]);
            unsigned a1 = __float_as_uint(Ps[(m0 + g + 8) * ATP + kk + tig    ]);
            unsigned a2 = __float_as_uint(Ps[(m0 + g    ) * ATP + kk + tig + 4]);
            unsigned a3 = __float_as_uint(Ps[(m0 + g + 8) * ATP + kk + tig + 4]);
#pragma unroll
            for (int in = 0; in < 4; in++) {
                unsigned b0 = __float_as_uint(Vs[(kk + tig    ) * ATP + n0 + in * 8 + g]);
                unsigned b1 = __float_as_uint(Vs[(kk + tig + 4) * ATP + n0 + in * 8 + g]);
                asm volatile(
                    "mma.sync.aligned.m16n8k8.row.col.f32.tf32.tf32.f32 "
                    "{%0,%1,%2,%3},{%4,%5,%6,%7},{%8,%9},{%0,%1,%2,%3};"
                    : "+f"(oacc[in][0]), "+f"(oacc[in][1]),
                      "+f"(oacc[in][2]), "+f"(oacc[in][3])
                    : "r"(a0), "r"(a1), "r"(a2), "r"(a3), "r"(b0), "r"(b1));
            }
        }
        __syncthreads();
    }

    int r0 = m0 + g, r1 = m0 + g + 8;
    float inv0 = 1.f / lrow[r0];
    float inv1 = 1.f / lrow[r1];
#pragma unroll
    for (int in = 0; in < 4; in++) {
        int c0 = n0 + in * 8 + 2 * tig;
        float2 o0, o1;
        o0.x = oacc[in][0] * inv0; o0.y = oacc[in][1] * inv0;
        o1.x = oacc[in][2] * inv1; o1.y = oacc[in][3] * inv1;
        *(float2*)(y + ((size_t)(b * Tt + q0 + r0)) * Dd + h * HD + c0) = o0;
        *(float2*)(y + ((size_t)(b * Tt + q0 + r1)) * Dd + h * HD + c0) = o1;
    }
}

// ---------------- residual + LayerNorm (2-input) ----------------
__global__ __launch_bounds__(256)
void ln_res_kernel(const float* __restrict__ a, const float* __restrict__ b,
                   const float* __restrict__ g, const float* __restrict__ be,
                   float* __restrict__ out) {
    __shared__ float buf[Dd];
    __shared__ float red[256];
    int r = blockIdx.x;
    int t = threadIdx.x;
    const float* ar = a + (size_t)r * Dd;
    const float* br = b + (size_t)r * Dd;

    float s = 0.f;
    for (int c = t; c < Dd; c += 256) {
        float vv = ar[c] + br[c];
        buf[c] = vv;
        s += vv;
    }
    red[t] = s; __syncthreads();
    for (int o = 128; o > 0; o >>= 1) { if (t < o) red[t] += red[t + o]; __syncthreads(); }
    float mu = red[0] / (float)Dd;
    __syncthreads();

    float s2 = 0.f;
    for (int c = t; c < Dd; c += 256) {
        float d = buf[c] - mu;
        s2 += d * d;
    }
    red[t] = s2; __syncthreads();
    for (int o = 128; o > 0; o >>= 1) { if (t < o) red[t] += red[t + o]; __syncthreads(); }
    float rstd = rsqrtf(red[0] / (float)Dd + 1e-5f);

    float* orr = out + (size_t)r * Dd;
    for (int c = t; c < Dd; c += 256)
        orr[c] = (buf[c] - mu) * rstd * g[c] + be[c];
}

// ---------------- residual + LayerNorm (4-input: FFN2 partials + residual) ----------------
__global__ __launch_bounds__(256)
void ln_res4_kernel(const float* __restrict__ a, const float* __restrict__ b,
                    const float* __restrict__ c2, const float* __restrict__ d2,
                    const float* __restrict__ g, const float* __restrict__ be,
                    float* __restrict__ out) {
    __shared__ float buf[Dd];
    __shared__ float red[256];
    int r = blockIdx.x;
    int t = threadIdx.x;
    const float* ar = a  + (size_t)r * Dd;
    const float* br = b  + (size_t)r * Dd;
    const float* cr = c2 + (size_t)r * Dd;
    const float* dr = d2 + (size_t)r * Dd;

    float s = 0.f;
    for (int c = t; c < Dd; c += 256) {
        float vv = ((ar[c] + br[c]) + cr[c]) + dr[c];
        buf[c] = vv;
        s += vv;
    }
    red[t] = s; __syncthreads();
    for (int o = 128; o > 0; o >>= 1) { if (t < o) red[t] += red[t + o]; __syncthreads(); }
    float mu = red[0] / (float)Dd;
    __syncthreads();

    float s2 = 0.f;
    for (int c = t; c < Dd; c += 256) {
        float d = buf[c] - mu;
        s2 += d * d;
    }
    red[t] = s2; __syncthreads();
    for (int o = 128; o > 0; o >>= 1) { if (t < o) red[t] += red[t + o]; __syncthreads(); }
    float rstd = rsqrtf(red[0] / (float)Dd + 1e-5f);

    float* orr = out + (size_t)r * Dd;
    for (int c = t; c < Dd; c += 256)
        orr[c] = (buf[c] - mu) * rstd * g[c] + be[c];
}

// ---------------- per-row cross-entropy ----------------
__global__ __launch_bounds__(256)
void rowloss_kernel(const float* __restrict__ logits, const int* __restrict__ tgt,
                    float* __restrict__ rl) {
    __shared__ float sm[256], sl[256];
    int r = blockIdx.x;
    int t = threadIdx.x;
    const float* lg = logits + (size_t)r * Vv;

    float m = -1e30f, l = 0.f;
    for (int c = t; c < Vv; c += 256) {
        float x = lg[c];
        if (x > m) { l = l * __expf(m - x) + 1.f; m = x; }
        else       { l += __expf(x - m); }
    }
    sm[t] = m; sl[t] = l; __syncthreads();
    for (int o = 128; o > 0; o >>= 1) {
        if (t < o) {
            float m1 = sm[t], m2 = sm[t + o];
            float M = fmaxf(m1, m2);
            sl[t] = sl[t] * __expf(m1 - M) + sl[t + o] * __expf(m2 - M);
            sm[t] = M;
        }
        __syncthreads();
    }
    if (t == 0)
        rl[r] = (sm[0] + logf(sl[0])) - lg[tgt[r]];
}

__global__ __launch_bounds__(256)
void meanloss_kernel(const float* __restrict__ rl, float* __restrict__ out) {
    __shared__ float red[256];
    int t = threadIdx.x;
    float s = 0.f;
    for (int i = t; i < BT; i += 256) s += rl[i];
    red[t] = s; __syncthreads();
    for (int o = 128; o > 0; o >>= 1) { if (t < o) red[t] += red[t + o]; __syncthreads(); }
    if (t == 0) out[0] = red[0] / (float)BT;
}

// ---------------- launch ----------------
extern "C" void kernel_launch(void* const* d_in, const int* in_sizes, int n_in,
                              void* d_out, int out_size) {
    const int*   idx    = (const int*)  d_in[0];
    const int*   tgt    = (const int*)  d_in[1];
    const float* tok    = (const float*)d_in[2];
    const float* pos    = (const float*)d_in[3];
    const float* Wq     = (const float*)d_in[4];
    const float* Wk     = (const float*)d_in[5];
    const float* Wv     = (const float*)d_in[6];
    const float* ln1g   = (const float*)d_in[7];
    const float* ln1b   = (const float*)d_in[8];
    const float* W1     = (const float*)d_in[9];
    const float* b1     = (const float*)d_in[10];
    const float* W2     = (const float*)d_in[11];
    const float* b2     = (const float*)d_in[12];
    const float* ln2g   = (const float*)d_in[13];
    const float* ln2b   = (const float*)d_in[14];
    const float* headw  = (const float*)d_in[15];
    const float* headb  = (const float*)d_in[16];
    float* out = (float*)d_out;

    float *x, *x2, *q, *k, *v, *y, *ff1, *rl, *wpad;
    cudaGetSymbolAddress((void**)&x,    g_x);
    cudaGetSymbolAddress((void**)&x2,   g_x2);
    cudaGetSymbolAddress((void**)&q,    g_q);
    cudaGetSymbolAddress((void**)&k,    g_k);
    cudaGetSymbolAddress((void**)&v,    g_v);
    cudaGetSymbolAddress((void**)&y,    g_y);
    cudaGetSymbolAddress((void**)&ff1,  g_ff1);
    cudaGetSymbolAddress((void**)&rl,   g_rl);
    cudaGetSymbolAddress((void**)&wpad, g_wpad);

    cudaFuncSetAttribute(attn_kernel,
                         cudaFuncAttributeMaxDynamicSharedMemorySize, ATTN_SMEM);

    embed_kernel<<<BT, 256>>>(idx, tok, pos, x);
    padw_kernel<<<Dd, 256>>>(headw, wpad);

    dim3 gQKV(18, BT / 128);
    dim3 gF(FF / 128, BT / 128);             // 24 x 32
    dim3 gF2(18, BT / 128);                  // 3 K-parts x 6 col-tiles
    dim3 gV(VP / 128, BT / 128);             // 393 x 32

    for (int l = 0; l < Ll; l++) {
        const float* wq = Wq + (size_t)l * Dd * Dd;
        const float* wk = Wk + (size_t)l * Dd * Dd;
        const float* wv = Wv + (size_t)l * Dd * Dd;
        const float* w1 = W1 + (size_t)l * Dd * FF;
        const float* w2 = W2 + (size_t)l * FF * Dd;

        qkv_kernel<<<gQKV, 256>>>(x, wq, wk, wv, q, k, v);

        attn_kernel<<<dim3(Tt / 64, Hh, Bb), 256, ATTN_SMEM>>>(q, k, v, y);

        ln_res_kernel<<<BT, 256>>>(y, x, ln1g + l * Dd, ln1b + l * Dd, x2);

        tgemm_kernel<2><<<gF, 256>>>(x2, w1, b1 + (size_t)l * FF, ff1, FF, Dd, FF);

        // split-K=3 FFN2 in one launch: partials -> y, q, k (q/k dead after attn)
        ffn2_kernel<<<gF2, 256>>>(ff1, w2, b2 + (size_t)l * Dd, y, q, k);

        ln_res4_kernel<<<BT, 256>>>(y, q, k, x2, ln2g + l * Dd, ln2b + l * Dd, x);
    }

    tgemm_kernel<1><<<gV, 256>>>(x, wpad, headb, out, Vv, Dd, VP);

    rowloss_kernel<<<BT, 256>>>(out, tgt, rl);
    meanloss_kernel<<<1, 256>>>(rl, out + (size_t)BT * Vv);
}

// round 12
// speedup vs baseline: 1.5326x; 1.0679x over previous
#include <cuda_runtime.h>
#include <cuda_bf16.h>
#include <math.h>

// ---------------- model constants ----------------
#define Vv 50257
#define VP 50304            // padded vocab (multiple of 128)
#define Dd 768
#define Hh 12
#define HD 64
#define Tt 1024
#define Ll 6
#define Bb 4
#define BT (Bb*Tt)          // 4096
#define FF (4*Dd)           // 3072

#define BM 128
#define BN 128
#define BKK 16
#define ATP 68              // attention smem row stride (floats)
#define KSPL 1024           // FFN2 split-K chunk (3 parts of 3072)

// ---------------- scratch (static device arrays; no allocation) ----------------
__device__ float g_x   [BT*Dd];
__device__ float g_x2  [BT*Dd];
__device__ float g_q   [BT*Dd];
__device__ float g_k   [BT*Dd];
__device__ float g_v   [BT*Dd];
__device__ float g_y   [BT*Dd];
__device__ float g_ff1 [BT*FF];
__device__ float g_rl  [BT];
__device__ float g_wpad[(size_t)Dd*VP];   // padded, pre-tf32 head weights

__device__ __forceinline__ float to_tf32(float x) {
    float y;
    asm("cvt.rna.tf32.f32 %0, %1;" : "=f"(y) : "f"(x));
    return y;
}

// ---------------- embedding ----------------
__global__ void embed_kernel(const int* __restrict__ idx,
                             const float* __restrict__ tok,
                             const float* __restrict__ pos,
                             float* __restrict__ x) {
    int r = blockIdx.x;
    int t = r & (Tt - 1);
    int token = idx[r];
    const float* tr = tok + (size_t)token * Dd;
    const float* pr = pos + (size_t)t * Dd;
    float* xr = x + (size_t)r * Dd;
    for (int c = threadIdx.x; c < Dd; c += blockDim.x)
        xr[c] = tr[c] + pr[c];
}

// ---------------- pad + pre-convert head weights ----------------
__global__ void padw_kernel(const float* __restrict__ w, float* __restrict__ wp) {
    int kk = blockIdx.x;             // 0..767
    const float* src = w + (size_t)kk * Vv;
    float* dst = wp + (size_t)kk * VP;
    for (int n = threadIdx.x; n < VP; n += blockDim.x)
        dst[n] = (n < Vv) ? to_tf32(src[n]) : 0.f;
}

// ---------------- TF32 tensor-core GEMM core (R3 mainloop, FROZEN) ----------------
template<int EPI>
__device__ __forceinline__ void gemm_core(
    const float* __restrict__ A, const float* __restrict__ Bm,
    const float* __restrict__ bias, float* __restrict__ C,
    int N, int K, int Astride, int Bstride, int row0, int col0)
{
    __shared__ float As[BKK][BM + 4];   // As[k][m]
    __shared__ float Bs[BKK][BN + 4];   // Bs[k][n]

    int t    = threadIdx.x;
    int wid  = t >> 5;
    int lane = t & 31;
    int g    = lane >> 2;
    int tig  = lane & 3;
    int m0w  = (wid & 1) * 64;
    int n0w  = (wid >> 1) * 32;

    const bool vec_ok = ((col0 + BN) <= Bstride) && ((Bstride & 3) == 0);

    float acc[4][4][4];
#pragma unroll
    for (int im = 0; im < 4; im++)
#pragma unroll
        for (int in = 0; in < 4; in++)
#pragma unroll
            for (int c = 0; c < 4; c++) acc[im][in][c] = 0.f;

    for (int k0 = 0; k0 < K; k0 += BKK) {
#pragma unroll
        for (int i = 0; i < 2; i++) {
            int idx = t + i * 256;
            int row = idx >> 2;
            int seg = (idx & 3) * 4;
            float4 a4 = *(const float4*)(A + (size_t)(row0 + row) * Astride + k0 + seg);
            As[seg + 0][row] = to_tf32(a4.x);
            As[seg + 1][row] = to_tf32(a4.y);
            As[seg + 2][row] = to_tf32(a4.z);
            As[seg + 3][row] = to_tf32(a4.w);
        }
        if (vec_ok) {
#pragma unroll
            for (int i = 0; i < 2; i++) {
                int idx = t + i * 256;
                int kr  = idx >> 5;
                int cs  = (idx & 31) * 4;
                float4 b4 = *(const float4*)(Bm + (size_t)(k0 + kr) * Bstride + col0 + cs);
                Bs[kr][cs + 0] = to_tf32(b4.x);
                Bs[kr][cs + 1] = to_tf32(b4.y);
                Bs[kr][cs + 2] = to_tf32(b4.z);
                Bs[kr][cs + 3] = to_tf32(b4.w);
            }
        } else {
#pragma unroll
            for (int i = 0; i < 8; i++) {
                int e = t + i * 256;
                int kr = e >> 7;
                int c  = e & 127;
                int col = col0 + c;
                Bs[kr][c] = (col < Bstride) ? to_tf32(Bm[(size_t)(k0 + kr) * Bstride + col]) : 0.f;
            }
        }
        __syncthreads();

#pragma unroll
        for (int ks = 0; ks < BKK; ks += 8) {
            unsigned af[4][4], bf[4][2];
#pragma unroll
            for (int im = 0; im < 4; im++) {
                int m = m0w + im * 16 + g;
                af[im][0] = __float_as_uint(As[ks + tig    ][m    ]);
                af[im][1] = __float_as_uint(As[ks + tig    ][m + 8]);
                af[im][2] = __float_as_uint(As[ks + tig + 4][m    ]);
                af[im][3] = __float_as_uint(As[ks + tig + 4][m + 8]);
            }
#pragma unroll
            for (int in = 0; in < 4; in++) {
                int n = n0w + in * 8 + g;
                bf[in][0] = __float_as_uint(Bs[ks + tig    ][n]);
                bf[in][1] = __float_as_uint(Bs[ks + tig + 4][n]);
            }
#pragma unroll
            for (int im = 0; im < 4; im++)
#pragma unroll
                for (int in = 0; in < 4; in++) {
                    asm volatile(
                        "mma.sync.aligned.m16n8k8.row.col.f32.tf32.tf32.f32 "
                        "{%0,%1,%2,%3},{%4,%5,%6,%7},{%8,%9},{%0,%1,%2,%3};"
                        : "+f"(acc[im][in][0]), "+f"(acc[im][in][1]),
                          "+f"(acc[im][in][2]), "+f"(acc[im][in][3])
                        : "r"(af[im][0]), "r"(af[im][1]), "r"(af[im][2]), "r"(af[im][3]),
                          "r"(bf[in][0]), "r"(bf[in][1]));
                }
        }
        __syncthreads();
    }

#pragma unroll
    for (int im = 0; im < 4; im++) {
        int r_lo = row0 + m0w + im * 16 + g;
        int r_hi = r_lo + 8;
#pragma unroll
        for (int in = 0; in < 4; in++) {
            int c_lo = col0 + n0w + in * 8 + 2 * tig;
            int c_hi = c_lo + 1;
            float v0 = acc[im][in][0], v1 = acc[im][in][1];
            float v2 = acc[im][in][2], v3 = acc[im][in][3];
            if (EPI >= 1) {
                if (c_lo < N) { v0 += bias[c_lo]; v2 += bias[c_lo]; }
                if (c_hi < N) { v1 += bias[c_hi]; v3 += bias[c_hi]; }
            }
            if (EPI == 2) {
                v0 = fmaxf(v0, 0.f); v1 = fmaxf(v1, 0.f);
                v2 = fmaxf(v2, 0.f); v3 = fmaxf(v3, 0.f);
            }
            size_t blo = (size_t)r_lo * N;
            size_t bhi = (size_t)r_hi * N;
            if (c_lo < N) { C[blo + c_lo] = v0; C[bhi + c_lo] = v2; }
            if (c_hi < N) { C[blo + c_hi] = v1; C[bhi + c_hi] = v3; }
        }
    }
}

template<int EPI>
__global__ __launch_bounds__(256)
void tgemm_kernel(const float* __restrict__ A, const float* __restrict__ Bm,
                  const float* __restrict__ bias, float* __restrict__ C,
                  int N, int K, int Bstride) {
    gemm_core<EPI>(A, Bm, bias, C, N, K, K, Bstride,
                   blockIdx.y * BM, blockIdx.x * BN);
}

// head GEMM with transposed grid: blockIdx.x = row-tile (fast), blockIdx.y = col-tile.
// Concurrent CTAs then share B col-tiles in L2 (32 row-CTAs per col-tile).
__global__ __launch_bounds__(256)
void tgemm_swap_kernel(const float* __restrict__ A, const float* __restrict__ Bm,
                       const float* __restrict__ bias, float* __restrict__ C,
                       int N, int K, int Bstride) {
    gemm_core<1>(A, Bm, bias, C, N, K, K, Bstride,
                 blockIdx.x * BM, blockIdx.y * BN);
}

// fused QKV: grid (18, 32)
__global__ __launch_bounds__(256)
void qkv_kernel(const float* __restrict__ x,
                const float* __restrict__ wq, const float* __restrict__ wk,
                const float* __restrict__ wv,
                float* __restrict__ q, float* __restrict__ k, float* __restrict__ v) {
    int ct  = blockIdx.x;
    int mat = ct / 6;
    int c   = ct % 6;
    const float* B = (mat == 0) ? wq : (mat == 1) ? wk : wv;
    float*       C = (mat == 0) ? q  : (mat == 1) ? k  : v;
    gemm_core<0>(x, B, nullptr, C, Dd, Dd, Dd, Dd, blockIdx.y * BM, c * BN);
}

// fused split-K FFN2: grid (18, 32)
__global__ __launch_bounds__(256)
void ffn2_kernel(const float* __restrict__ ff1, const float* __restrict__ w2,
                 const float* __restrict__ bias,
                 float* __restrict__ y0, float* __restrict__ y1, float* __restrict__ y2) {
    int p = blockIdx.x / 6;
    int c = blockIdx.x % 6;
    const float* A = ff1 + p * KSPL;
    const float* B = w2 + (size_t)p * KSPL * Dd;
    int row0 = blockIdx.y * BM, col0 = c * BN;
    if (p == 0)      gemm_core<1>(A, B, bias,    y0, Dd, KSPL, FF, Dd, row0, col0);
    else if (p == 1) gemm_core<0>(A, B, nullptr, y1, Dd, KSPL, FF, Dd, row0, col0);
    else             gemm_core<0>(A, B, nullptr, y2, Dd, KSPL, FF, Dd, row0, col0);
}

// ---------------- tensor-core causal flash attention (R8-verified, FROZEN) ----------------
#define ATTN_SMEM ((4*64*ATP + 64*3 + 2*64*2) * 4)
__global__ __launch_bounds__(256)
void attn_kernel(const float* __restrict__ q, const float* __restrict__ k,
                 const float* __restrict__ v, float* __restrict__ y) {
    extern __shared__ float asmem[];
    float* Qs   = asmem;               // [64][ATP]
    float* Ks   = Qs + 64 * ATP;
    float* Vs   = Ks + 64 * ATP;
    float* Ps   = Vs + 64 * ATP;
    float* mrow = Ps + 64 * ATP;
    float* lrow = mrow + 64;
    float* cfac = lrow + 64;
    float* pmax = cfac + 64;           // [2][64]
    float* psum = pmax + 128;          // [2][64]

    int t    = threadIdx.x;
    int wid  = t >> 5;
    int lane = t & 31;
    int g    = lane >> 2;
    int tig  = lane & 3;
    int m0   = (wid & 3) * 16;
    int n0   = (wid >> 2) * 32;
    int nch  = wid >> 2;

    int q0 = blockIdx.x * 64;
    int h  = blockIdx.y;
    int b  = blockIdx.z;

    for (int i = t; i < 64 * 16; i += 256) {
        int r = i >> 4, c4 = i & 15;
        float4 qv = *(const float4*)(q + ((size_t)(b * Tt + q0 + r)) * Dd + h * HD + c4 * 4);
        float* d = Qs + r * ATP + c4 * 4;
        d[0] = to_tf32(qv.x); d[1] = to_tf32(qv.y);
        d[2] = to_tf32(qv.z); d[3] = to_tf32(qv.w);
    }
    if (t < 64) { mrow[t] = -1e30f; lrow[t] = 0.f; }

    float oacc[4][4];
#pragma unroll
    for (int in = 0; in < 4; in++)
#pragma unroll
        for (int c = 0; c < 4; c++) oacc[in][c] = 0.f;

    int ntiles = blockIdx.x + 1;
    __syncthreads();

    for (int jt = 0; jt < ntiles; jt++) {
        int s0 = jt * 64;
        bool diag = (jt == ntiles - 1);

        for (int i = t; i < 64 * 16; i += 256) {
            int r = i >> 4, c4 = i & 15;
            size_t gb = ((size_t)(b * Tt + s0 + r)) * Dd + h * HD + c4 * 4;
            float4 kv = *(const float4*)(k + gb);
            float4 vv = *(const float4*)(v + gb);
            float* dk = Ks + r * ATP + c4 * 4;
            dk[0] = to_tf32(kv.x); dk[1] = to_tf32(kv.y);
            dk[2] = to_tf32(kv.z); dk[3] = to_tf32(kv.w);
            float* dv = Vs + r * ATP + c4 * 4;
            dv[0] = to_tf32(vv.x); dv[1] = to_tf32(vv.y);
            dv[2] = to_tf32(vv.z); dv[3] = to_tf32(vv.w);
        }
        __syncthreads();

        float sacc[4][4];
#pragma unroll
        for (int in = 0; in < 4; in++)
#pragma unroll
            for (int c = 0; c < 4; c++) sacc[in][c] = 0.f;
#pragma unroll
        for (int k8 = 0; k8 < 8; k8++) {
            int kk = k8 * 8;
            unsigned a0 = __float_as_uint(Qs[(m0 + g    ) * ATP + kk + tig    ]);
            unsigned a1 = __float_as_uint(Qs[(m0 + g + 8) * ATP + kk + tig    ]);
            unsigned a2 = __float_as_uint(Qs[(m0 + g    ) * ATP + kk + tig + 4]);
            unsigned a3 = __float_as_uint(Qs[(m0 + g + 8) * ATP + kk + tig + 4]);
#pragma unroll
            for (int in = 0; in < 4; in++) {
                unsigned b0 = __float_as_uint(Ks[(n0 + in * 8 + g) * ATP + kk + tig    ]);
                unsigned b1 = __float_as_uint(Ks[(n0 + in * 8 + g) * ATP + kk + tig + 4]);
                asm volatile(
                    "mma.sync.aligned.m16n8k8.row.col.f32.tf32.tf32.f32 "
                    "{%0,%1,%2,%3},{%4,%5,%6,%7},{%8,%9},{%0,%1,%2,%3};"
                    : "+f"(sacc[in][0]), "+f"(sacc[in][1]),
                      "+f"(sacc[in][2]), "+f"(sacc[in][3])
                    : "r"(a0), "r"(a1), "r"(a2), "r"(a3), "r"(b0), "r"(b1));
            }
        }

        int r0 = m0 + g, r1 = m0 + g + 8;
#pragma unroll
        for (int in = 0; in < 4; in++) {
            int c0 = n0 + in * 8 + 2 * tig, c1 = c0 + 1;
            sacc[in][0] *= 0.125f; sacc[in][1] *= 0.125f;
            sacc[in][2] *= 0.125f; sacc[in][3] *= 0.125f;
            if (diag) {
                if (c0 > r0) sacc[in][0] = -1e30f;
                if (c1 > r0) sacc[in][1] = -1e30f;
                if (c0 > r1) sacc[in][2] = -1e30f;
                if (c1 > r1) sacc[in][3] = -1e30f;
            }
        }

        float rmax0 = -1e30f, rmax1 = -1e30f;
#pragma unroll
        for (int in = 0; in < 4; in++) {
            rmax0 = fmaxf(rmax0, fmaxf(sacc[in][0], sacc[in][1]));
            rmax1 = fmaxf(rmax1, fmaxf(sacc[in][2], sacc[in][3]));
        }
        rmax0 = fmaxf(rmax0, __shfl_xor_sync(0xffffffffu, rmax0, 1));
        rmax0 = fmaxf(rmax0, __shfl_xor_sync(0xffffffffu, rmax0, 2));
        rmax1 = fmaxf(rmax1, __shfl_xor_sync(0xffffffffu, rmax1, 1));
        rmax1 = fmaxf(rmax1, __shfl_xor_sync(0xffffffffu, rmax1, 2));
        if (tig == 0) {
            pmax[nch * 64 + r0] = rmax0;
            pmax[nch * 64 + r1] = rmax1;
        }
        __syncthreads();

        if (t < 64) {
            float nm = fmaxf(mrow[t], fmaxf(pmax[t], pmax[64 + t]));
            cfac[t] = __expf(mrow[t] - nm);
            mrow[t] = nm;
        }
        __syncthreads();

        float nm0 = mrow[r0], nm1 = mrow[r1];
        float rs0 = 0.f, rs1 = 0.f;
#pragma unroll
        for (int in = 0; in < 4; in++) {
            int c0 = n0 + in * 8 + 2 * tig;
            float p0 = __expf(sacc[in][0] - nm0);
            float p1 = __expf(sacc[in][1] - nm0);
            float p2 = __expf(sacc[in][2] - nm1);
            float p3 = __expf(sacc[in][3] - nm1);
            rs0 += p0 + p1; rs1 += p2 + p3;
            Ps[r0 * ATP + c0    ] = to_tf32(p0);
            Ps[r0 * ATP + c0 + 1] = to_tf32(p1);
            Ps[r1 * ATP + c0    ] = to_tf32(p2);
            Ps[r1 * ATP + c0 + 1] = to_tf32(p3);
        }
        rs0 += __shfl_xor_sync(0xffffffffu, rs0, 1);
        rs0 += __shfl_xor_sync(0xffffffffu, rs0, 2);
        rs1 += __shfl_xor_sync(0xffffffffu, rs1, 1);
        rs1 += __shfl_xor_sync(0xffffffffu, rs1, 2);
        if (tig == 0) {
            psum[nch * 64 + r0] = rs0;
            psum[nch * 64 + r1] = rs1;
        }
        __syncthreads();

        if (t < 64) lrow[t] = lrow[t] * cfac[t] + psum[t] + psum[64 + t];

        float corr0 = cfac[r0], corr1 = cfac[r1];
#pragma unroll
        for (int in = 0; in < 4; in++) {
            oacc[in][0] *= corr0; oacc[in][1] *= corr0;
            oacc[in][2] *= corr1; oacc[in][3] *= corr1;
        }

#pragma unroll
        for (int k8 = 0; k8 < 8; k8++) {
            int kk = k8 * 8;
            unsigned a0 = __float_as_uint(Ps[(m0 + g    ) * ATP + kk + tig    ]);
            unsigned a1 = __float_as_uint(Ps[(m0 + g + 8) * ATP + kk + tig    ]);
            unsigned a2 = __float_as_uint(Ps[(m0 + g    ) * ATP + kk + tig + 4]);
            unsigned a3 = __float_as_uint(Ps[(m0 + g + 8) * ATP + kk + tig + 4]);
#pragma unroll
            for (int in = 0; in < 4; in++) {
                unsigned b0 = __float_as_uint(Vs[(kk + tig    ) * ATP + n0 + in * 8 + g]);
                unsigned b1 = __float_as_uint(Vs[(kk + tig + 4) * ATP + n0 + in * 8 + g]);
                asm volatile(
                    "mma.sync.aligned.m16n8k8.row.col.f32.tf32.tf32.f32 "
                    "{%0,%1,%2,%3},{%4,%5,%6,%7},{%8,%9},{%0,%1,%2,%3};"
                    : "+f"(oacc[in][0]), "+f"(oacc[in][1]),
                      "+f"(oacc[in][2]), "+f"(oacc[in][3])
                    : "r"(a0), "r"(a1), "r"(a2), "r"(a3), "r"(b0), "r"(b1));
            }
        }
        __syncthreads();
    }

    int r0 = m0 + g, r1 = m0 + g + 8;
    float inv0 = 1.f / lrow[r0];
    float inv1 = 1.f / lrow[r1];
#pragma unroll
    for (int in = 0; in < 4; in++) {
        int c0 = n0 + in * 8 + 2 * tig;
        float2 o0, o1;
        o0.x = oacc[in][0] * inv0; o0.y = oacc[in][1] * inv0;
        o1.x = oacc[in][2] * inv1; o1.y = oacc[in][3] * inv1;
        *(float2*)(y + ((size_t)(b * Tt + q0 + r0)) * Dd + h * HD + c0) = o0;
        *(float2*)(y + ((size_t)(b * Tt + q0 + r1)) * Dd + h * HD + c0) = o1;
    }
}

// ---------------- residual + LayerNorm, vectorized (192 thr, 1 float4/thread) ----------------
// NIN = number of summed inputs (2 or 4)
template<int NIN>
__device__ __forceinline__ void ln_core(
    const float* a, const float* b, const float* c2, const float* d2,
    const float* __restrict__ g, const float* __restrict__ be,
    float* out) {
    __shared__ float wred[6];
    __shared__ float stat;
    int r = blockIdx.x;
    int t = threadIdx.x;       // 0..191
    int lane = t & 31, wrp = t >> 5;

    float4 v = ((const float4*)(a + (size_t)r * Dd))[t];
    {
        float4 u = ((const float4*)(b + (size_t)r * Dd))[t];
        v.x += u.x; v.y += u.y; v.z += u.z; v.w += u.w;
    }
    if (NIN == 4) {
        float4 u = ((const float4*)(c2 + (size_t)r * Dd))[t];
        v.x += u.x; v.y += u.y; v.z += u.z; v.w += u.w;
        float4 w = ((const float4*)(d2 + (size_t)r * Dd))[t];
        v.x += w.x; v.y += w.y; v.z += w.z; v.w += w.w;
    }

    float s = (v.x + v.y) + (v.z + v.w);
#pragma unroll
    for (int o = 16; o > 0; o >>= 1) s += __shfl_xor_sync(0xffffffffu, s, o);
    if (lane == 0) wred[wrp] = s;
    __syncthreads();
    if (t == 0) {
        float tot = ((wred[0] + wred[1]) + (wred[2] + wred[3])) + (wred[4] + wred[5]);
        stat = tot / (float)Dd;
    }
    __syncthreads();
    float mu = stat;

    float dx = v.x - mu, dy = v.y - mu, dz = v.z - mu, dw = v.w - mu;
    float s2 = (dx * dx + dy * dy) + (dz * dz + dw * dw);
#pragma unroll
    for (int o = 16; o > 0; o >>= 1) s2 += __shfl_xor_sync(0xffffffffu, s2, o);
    __syncthreads();               // protect wred reuse
    if (lane == 0) wred[wrp] = s2;
    __syncthreads();
    if (t == 0) {
        float tot = ((wred[0] + wred[1]) + (wred[2] + wred[3])) + (wred[4] + wred[5]);
        stat = rsqrtf(tot / (float)Dd + 1e-5f);
    }
    __syncthreads();
    float rstd = stat;

    float4 gv = ((const float4*)g)[t];
    float4 bv = ((const float4*)be)[t];
    float4 o4;
    o4.x = dx * rstd * gv.x + bv.x;
    o4.y = dy * rstd * gv.y + bv.y;
    o4.z = dz * rstd * gv.z + bv.z;
    o4.w = dw * rstd * gv.w + bv.w;
    ((float4*)(out + (size_t)r * Dd))[t] = o4;
}

__global__ __launch_bounds__(192)
void ln_res_kernel(const float* __restrict__ a, const float* __restrict__ b,
                   const float* __restrict__ g, const float* __restrict__ be,
                   float* __restrict__ out) {
    ln_core<2>(a, b, nullptr, nullptr, g, be, out);
}

__global__ __launch_bounds__(192)
void ln_res4_kernel(const float* __restrict__ a, const float* __restrict__ b,
                    const float* __restrict__ c2, const float* __restrict__ d2,
                    const float* __restrict__ g, const float* __restrict__ be,
                    float* __restrict__ out) {
    ln_core<4>(a, b, c2, d2, g, be, out);
}

// ---------------- per-row cross-entropy (float4 main loop, alignment-peeled) ----------------
__global__ __launch_bounds__(256)
void rowloss_kernel(const float* __restrict__ logits, const int* __restrict__ tgt,
                    float* __restrict__ rl) {
    __shared__ float sm[256], sl[256];
    int r = blockIdx.x;
    int t = threadIdx.x;
    const float* lg = logits + (size_t)r * Vv;

    float m = -1e30f, l = 0.f;
    auto accum = [&](float x) {
        if (x > m) { l = l * __expf(m - x) + 1.f; m = x; }
        else       { l += __expf(x - m); }
    };

    // row base alignment: (r*Vv) % 4 == r % 4 floats (Vv odd)
    int skip = (4 - (r & 3)) & 3;
    if (t < skip) accum(lg[t]);
    const float4* lg4 = (const float4*)(lg + skip);
    int n4 = (Vv - skip) >> 2;
    for (int i = t; i < n4; i += 256) {
        float4 x4 = lg4[i];
        accum(x4.x); accum(x4.y); accum(x4.z); accum(x4.w);
    }
    int tail = skip + n4 * 4 + t;
    if (tail < Vv) accum(lg[tail]);

    sm[t] = m; sl[t] = l; __syncthreads();
    for (int o = 128; o > 0; o >>= 1) {
        if (t < o) {
            float m1 = sm[t], m2 = sm[t + o];
            float M = fmaxf(m1, m2);
            sl[t] = sl[t] * __expf(m1 - M) + sl[t + o] * __expf(m2 - M);
            sm[t] = M;
        }
        __syncthreads();
    }
    if (t == 0)
        rl[r] = (sm[0] + logf(sl[0])) - lg[tgt[r]];
}

__global__ __launch_bounds__(256)
void meanloss_kernel(const float* __restrict__ rl, float* __restrict__ out) {
    __shared__ float red[256];
    int t = threadIdx.x;
    float s = 0.f;
    for (int i = t; i < BT; i += 256) s += rl[i];
    red[t] = s; __syncthreads();
    for (int o = 128; o > 0; o >>= 1) { if (t < o) red[t] += red[t + o]; __syncthreads(); }
    if (t == 0) out[0] = red[0] / (float)BT;
}

// ---------------- launch ----------------
extern "C" void kernel_launch(void* const* d_in, const int* in_sizes, int n_in,
                              void* d_out, int out_size) {
    const int*   idx    = (const int*)  d_in[0];
    const int*   tgt    = (const int*)  d_in[1];
    const float* tok    = (const float*)d_in[2];
    const float* pos    = (const float*)d_in[3];
    const float* Wq     = (const float*)d_in[4];
    const float* Wk     = (const float*)d_in[5];
    const float* Wv     = (const float*)d_in[6];
    const float* ln1g   = (const float*)d_in[7];
    const float* ln1b   = (const float*)d_in[8];
    const float* W1     = (const float*)d_in[9];
    const float* b1     = (const float*)d_in[10];
    const float* W2     = (const float*)d_in[11];
    const float* b2     = (const float*)d_in[12];
    const float* ln2g   = (const float*)d_in[13];
    const float* ln2b   = (const float*)d_in[14];
    const float* headw  = (const float*)d_in[15];
    const float* headb  = (const float*)d_in[16];
    float* out = (float*)d_out;

    float *x, *x2, *q, *k, *v, *y, *ff1, *rl, *wpad;
    cudaGetSymbolAddress((void**)&x,    g_x);
    cudaGetSymbolAddress((void**)&x2,   g_x2);
    cudaGetSymbolAddress((void**)&q,    g_q);
    cudaGetSymbolAddress((void**)&k,    g_k);
    cudaGetSymbolAddress((void**)&v,    g_v);
    cudaGetSymbolAddress((void**)&y,    g_y);
    cudaGetSymbolAddress((void**)&ff1,  g_ff1);
    cudaGetSymbolAddress((void**)&rl,   g_rl);
    cudaGetSymbolAddress((void**)&wpad, g_wpad);

    cudaFuncSetAttribute(attn_kernel,
                         cudaFuncAttributeMaxDynamicSharedMemorySize, ATTN_SMEM);

    embed_kernel<<<BT, 256>>>(idx, tok, pos, x);
    padw_kernel<<<Dd, 256>>>(headw, wpad);

    dim3 gQKV(18, BT / 128);
    dim3 gF(FF / 128, BT / 128);             // 24 x 32
    dim3 gF2(18, BT / 128);                  // 3 K-parts x 6 col-tiles
    dim3 gVs(BT / 128, VP / 128);            // 32 x 393 (row-fast for B L2 sharing)

    for (int l = 0; l < Ll; l++) {
        const float* wq = Wq + (size_t)l * Dd * Dd;
        const float* wk = Wk + (size_t)l * Dd * Dd;
        const float* wv = Wv + (size_t)l * Dd * Dd;
        const float* w1 = W1 + (size_t)l * Dd * FF;
        const float* w2 = W2 + (size_t)l * FF * Dd;

        qkv_kernel<<<gQKV, 256>>>(x, wq, wk, wv, q, k, v);

        attn_kernel<<<dim3(Tt / 64, Hh, Bb), 256, ATTN_SMEM>>>(q, k, v, y);

        ln_res_kernel<<<BT, 192>>>(y, x, ln1g + l * Dd, ln1b + l * Dd, x2);

        tgemm_kernel<2><<<gF, 256>>>(x2, w1, b1 + (size_t)l * FF, ff1, FF, Dd, FF);

        ffn2_kernel<<<gF2, 256>>>(ff1, w2, b2 + (size_t)l * Dd, y, q, k);

        ln_res4_kernel<<<BT, 192>>>(y, q, k, x2, ln2g + l * Dd, ln2b + l * Dd, x);
    }

    // head: transposed grid, padded tf32 B with stride VP; stores guarded to N=Vv
    tgemm_swap_kernel<<<gVs, 256>>>(x, wpad, headb, out, Vv, Dd, VP);

    rowloss_kernel<<<BT, 256>>>(out, tgt, rl);
    meanloss_kernel<<<1, 256>>>(rl, out + (size_t)BT * Vv);
}

// round 17
// speedup vs baseline: 1.9688x; 1.2846x over previous
#include <cuda_runtime.h>
#include <cuda_bf16.h>
#include <math.h>

// ---------------- model constants ----------------
#define Vv 50257
#define VP 50304            // padded vocab (multiple of 128)
#define Dd 768
#define Hh 12
#define HD 64
#define Tt 1024
#define Ll 6
#define Bb 4
#define BT (Bb*Tt)          // 4096
#define FF (4*Dd)           // 3072

#define BM 128
#define BN 128
#define BKK 16
#define AP 20               // A smem row stride (floats): 80B, 16B-aligned, conflict-free
#define ATP 68              // attention smem row stride (floats)
#define KSPL 1024           // FFN2 split-K chunk

// ---------------- scratch (static device arrays; no allocation) ----------------
__device__ float g_x   [BT*Dd];
__device__ float g_xt  [BT*Dd];            // tf32-rounded copy of x
__device__ float g_x2  [BT*Dd];
__device__ float g_x2t [BT*Dd];            // tf32-rounded copy of x2
__device__ float g_q   [BT*Dd];
__device__ float g_k   [BT*Dd];
__device__ float g_v   [BT*Dd];
__device__ float g_y   [BT*Dd];
__device__ float g_ff1 [BT*FF];            // stored pre-rounded tf32
__device__ float g_rl  [BT];
__device__ float g_wpad[(size_t)Dd*VP];    // padded, pre-tf32 head weights
__device__ float g_wqt [(size_t)Ll*Dd*Dd]; // tf32 weights
__device__ float g_wkt [(size_t)Ll*Dd*Dd];
__device__ float g_wvt [(size_t)Ll*Dd*Dd];
__device__ float g_w1t [(size_t)Ll*Dd*FF];
__device__ float g_w2t [(size_t)Ll*FF*Dd];

__device__ __forceinline__ float to_tf32(float x) {
    float y;
    asm("cvt.rna.tf32.f32 %0, %1;" : "=f"(y) : "f"(x));
    return y;
}

// ---- cp.async helpers ----
#define CP_A16(dst_u32, src_ptr) \
    asm volatile("cp.async.cg.shared.global [%0], [%1], 16;" \
                 :: "r"(dst_u32), "l"(src_ptr) : "memory")
#define CP_COMMIT()  asm volatile("cp.async.commit_group;" ::: "memory")
#define CP_WAIT1()   asm volatile("cp.async.wait_group 1;" ::: "memory")
#define CP_WAIT0()   asm volatile("cp.async.wait_group 0;" ::: "memory")

// ---------------- embedding (writes fp32 x + tf32 xt) ----------------
__global__ void embed_kernel(const int* __restrict__ idx,
                             const float* __restrict__ tok,
                             const float* __restrict__ pos,
                             float* __restrict__ x, float* __restrict__ xt) {
    int r = blockIdx.x;
    int t = r & (Tt - 1);
    int token = idx[r];
    const float* tr = tok + (size_t)token * Dd;
    const float* pr = pos + (size_t)t * Dd;
    float* xr = x + (size_t)r * Dd;
    float* xtr = xt + (size_t)r * Dd;
    for (int c = threadIdx.x; c < Dd; c += blockDim.x) {
        float v = tr[c] + pr[c];
        xr[c] = v;
        xtr[c] = to_tf32(v);
    }
}

// ---------------- pad + pre-convert head weights ----------------
__global__ void padw_kernel(const float* __restrict__ w, float* __restrict__ wp) {
    int kk = blockIdx.x;
    const float* src = w + (size_t)kk * Vv;
    float* dst = wp + (size_t)kk * VP;
    for (int n = threadIdx.x; n < VP; n += blockDim.x)
        dst[n] = (n < Vv) ? to_tf32(src[n]) : 0.f;
}

// ---------------- elementwise tf32 convert (float4) ----------------
__global__ void cvtw_kernel(const float* __restrict__ src, float* __restrict__ dst, int n4) {
    int i = blockIdx.x * 256 + threadIdx.x;
    if (i < n4) {
        float4 v = ((const float4*)src)[i];
        v.x = to_tf32(v.x); v.y = to_tf32(v.y);
        v.z = to_tf32(v.z); v.w = to_tf32(v.w);
        ((float4*)dst)[i] = v;
    }
}

// ---------------- TF32 GEMM core, cp.async 2-stage pipeline ----------------
// Inputs A, B are PRE-ROUNDED tf32 values in fp32 storage. All strides % 4 == 0,
// all tiles fully in-range in B (pads/guards handled upstream).
// A stored untransposed in smem: Am[buf][m][k] stride AP.
// EPI: 0 none, 1 +bias, 3 +bias+relu+tf32-round
template<int EPI>
__device__ __forceinline__ void gemm_core(
    const float* __restrict__ A, const float* __restrict__ Bm,
    const float* __restrict__ bias, float* __restrict__ C,
    int N, int K, int Astride, int Bstride, int row0, int col0)
{
    __shared__ float Am[2][BM][AP];       // 20.0 KB
    __shared__ float Bs[2][BKK][BN + 4];  // 16.5 KB

    int t    = threadIdx.x;
    int wid  = t >> 5;
    int lane = t & 31;
    int g    = lane >> 2;
    int tig  = lane & 3;
    int m0w  = (wid & 1) * 64;
    int n0w  = (wid >> 1) * 32;

    // per-thread fill coordinates
    const int arow0 = (t + 0)   >> 2, aseg0 = ((t + 0)   & 3) * 4;
    const int arow1 = (t + 256) >> 2, aseg1 = ((t + 256) & 3) * 4;
    const int bkr0  = (t + 0)   >> 5, bcs0  = ((t + 0)   & 31) * 4;
    const int bkr1  = (t + 256) >> 5, bcs1  = ((t + 256) & 31) * 4;

    float acc[4][4][4];
#pragma unroll
    for (int im = 0; im < 4; im++)
#pragma unroll
        for (int in = 0; in < 4; in++)
#pragma unroll
            for (int c = 0; c < 4; c++) acc[im][in][c] = 0.f;

    auto fill_async = [&](int buf, int k0) {
        unsigned da0 = (unsigned)__cvta_generic_to_shared(&Am[buf][arow0][aseg0]);
        unsigned da1 = (unsigned)__cvta_generic_to_shared(&Am[buf][arow1][aseg1]);
        CP_A16(da0, A + (size_t)(row0 + arow0) * Astride + k0 + aseg0);
        CP_A16(da1, A + (size_t)(row0 + arow1) * Astride + k0 + aseg1);
        unsigned db0 = (unsigned)__cvta_generic_to_shared(&Bs[buf][bkr0][bcs0]);
        unsigned db1 = (unsigned)__cvta_generic_to_shared(&Bs[buf][bkr1][bcs1]);
        CP_A16(db0, Bm + (size_t)(k0 + bkr0) * Bstride + col0 + bcs0);
        CP_A16(db1, Bm + (size_t)(k0 + bkr1) * Bstride + col0 + bcs1);
    };

    auto compute = [&](int buf) {
#pragma unroll
        for (int ks = 0; ks < BKK; ks += 8) {
            unsigned af[4][4], bf[4][2];
#pragma unroll
            for (int im = 0; im < 4; im++) {
                int m = m0w + im * 16 + g;
                af[im][0] = __float_as_uint(Am[buf][m    ][ks + tig    ]);
                af[im][1] = __float_as_uint(Am[buf][m + 8][ks + tig    ]);
                af[im][2] = __float_as_uint(Am[buf][m    ][ks + tig + 4]);
                af[im][3] = __float_as_uint(Am[buf][m + 8][ks + tig + 4]);
            }
#pragma unroll
            for (int in = 0; in < 4; in++) {
                int n = n0w + in * 8 + g;
                bf[in][0] = __float_as_uint(Bs[buf][ks + tig    ][n]);
                bf[in][1] = __float_as_uint(Bs[buf][ks + tig + 4][n]);
            }
#pragma unroll
            for (int im = 0; im < 4; im++)
#pragma unroll
                for (int in = 0; in < 4; in++) {
                    asm volatile(
                        "mma.sync.aligned.m16n8k8.row.col.f32.tf32.tf32.f32 "
                        "{%0,%1,%2,%3},{%4,%5,%6,%7},{%8,%9},{%0,%1,%2,%3};"
                        : "+f"(acc[im][in][0]), "+f"(acc[im][in][1]),
                          "+f"(acc[im][in][2]), "+f"(acc[im][in][3])
                        : "r"(af[im][0]), "r"(af[im][1]), "r"(af[im][2]), "r"(af[im][3]),
                          "r"(bf[in][0]), "r"(bf[in][1]));
                }
        }
    };

    const int nk = K / BKK;
    fill_async(0, 0);
    CP_COMMIT();
    for (int it = 0; it < nk; it++) {
        if (it + 1 < nk) {
            fill_async((it + 1) & 1, (it + 1) * BKK);
            CP_COMMIT();
            CP_WAIT1();
        } else {
            CP_WAIT0();
        }
        __syncthreads();
        compute(it & 1);
        __syncthreads();
    }

    // ---- epilogue ----
#pragma unroll
    for (int im = 0; im < 4; im++) {
        int r_lo = row0 + m0w + im * 16 + g;
        int r_hi = r_lo + 8;
#pragma unroll
        for (int in = 0; in < 4; in++) {
            int c_lo = col0 + n0w + in * 8 + 2 * tig;
            int c_hi = c_lo + 1;
            float v0 = acc[im][in][0], v1 = acc[im][in][1];
            float v2 = acc[im][in][2], v3 = acc[im][in][3];
            if (EPI >= 1) {
                if (c_lo < N) { v0 += bias[c_lo]; v2 += bias[c_lo]; }
                if (c_hi < N) { v1 += bias[c_hi]; v3 += bias[c_hi]; }
            }
            if (EPI == 3) {
                v0 = to_tf32(fmaxf(v0, 0.f)); v1 = to_tf32(fmaxf(v1, 0.f));
                v2 = to_tf32(fmaxf(v2, 0.f)); v3 = to_tf32(fmaxf(v3, 0.f));
            }
            size_t blo = (size_t)r_lo * N;
            size_t bhi = (size_t)r_hi * N;
            if (c_lo < N) { C[blo + c_lo] = v0; C[bhi + c_lo] = v2; }
            if (c_hi < N) { C[blo + c_hi] = v1; C[bhi + c_hi] = v3; }
        }
    }
}

template<int EPI>
__global__ __launch_bounds__(256)
void tgemm_kernel(const float* __restrict__ A, const float* __restrict__ Bm,
                  const float* __restrict__ bias, float* __restrict__ C,
                  int N, int K, int Bstride) {
    gemm_core<EPI>(A, Bm, bias, C, N, K, K, Bstride,
                   blockIdx.y * BM, blockIdx.x * BN);
}

// head GEMM, transposed grid (row-tile fast) for B L2 sharing
__global__ __launch_bounds__(256)
void tgemm_swap_kernel(const float* __restrict__ A, const float* __restrict__ Bm,
                       const float* __restrict__ bias, float* __restrict__ C,
                       int N, int K, int Bstride) {
    gemm_core<1>(A, Bm, bias, C, N, K, K, Bstride,
                 blockIdx.x * BM, blockIdx.y * BN);
}

// fused QKV: grid (18, 32)
__global__ __launch_bounds__(256)
void qkv_kernel(const float* __restrict__ xt,
                const float* __restrict__ wq, const float* __restrict__ wk,
                const float* __restrict__ wv,
                float* __restrict__ q, float* __restrict__ k, float* __restrict__ v) {
    int ct  = blockIdx.x;
    int mat = ct / 6;
    int c   = ct % 6;
    const float* B = (mat == 0) ? wq : (mat == 1) ? wk : wv;
    float*       C = (mat == 0) ? q  : (mat == 1) ? k  : v;
    gemm_core<0>(xt, B, nullptr, C, Dd, Dd, Dd, Dd, blockIdx.y * BM, c * BN);
}

// fused split-K FFN2: grid (18, 32)
__global__ __launch_bounds__(256)
void ffn2_kernel(const float* __restrict__ ff1, const float* __restrict__ w2,
                 const float* __restrict__ bias,
                 float* __restrict__ y0, float* __restrict__ y1, float* __restrict__ y2) {
    int p = blockIdx.x / 6;
    int c = blockIdx.x % 6;
    const float* A = ff1 + p * KSPL;
    const float* B = w2 + (size_t)p * KSPL * Dd;
    int row0 = blockIdx.y * BM, col0 = c * BN;
    if (p == 0)      gemm_core<1>(A, B, bias,    y0, Dd, KSPL, FF, Dd, row0, col0);
    else if (p == 1) gemm_core<0>(A, B, nullptr, y1, Dd, KSPL, FF, Dd, row0, col0);
    else             gemm_core<0>(A, B, nullptr, y2, Dd, KSPL, FF, Dd, row0, col0);
}

// ---------------- tensor-core causal flash attention (R8-verified, FROZEN) ----------------
#define ATTN_SMEM ((4*64*ATP + 64*3 + 2*64*2) * 4)
__global__ __launch_bounds__(256)
void attn_kernel(const float* __restrict__ q, const float* __restrict__ k,
                 const float* __restrict__ v, float* __restrict__ y) {
    extern __shared__ float asmem[];
    float* Qs   = asmem;
    float* Ks   = Qs + 64 * ATP;
    float* Vs   = Ks + 64 * ATP;
    float* Ps   = Vs + 64 * ATP;
    float* mrow = Ps + 64 * ATP;
    float* lrow = mrow + 64;
    float* cfac = lrow + 64;
    float* pmax = cfac + 64;
    float* psum = pmax + 128;

    int t    = threadIdx.x;
    int wid  = t >> 5;
    int lane = t & 31;
    int g    = lane >> 2;
    int tig  = lane & 3;
    int m0   = (wid & 3) * 16;
    int n0   = (wid >> 2) * 32;
    int nch  = wid >> 2;

    int q0 = blockIdx.x * 64;
    int h  = blockIdx.y;
    int b  = blockIdx.z;

    for (int i = t; i < 64 * 16; i += 256) {
        int r = i >> 4, c4 = i & 15;
        float4 qv = *(const float4*)(q + ((size_t)(b * Tt + q0 + r)) * Dd + h * HD + c4 * 4);
        float* d = Qs + r * ATP + c4 * 4;
        d[0] = to_tf32(qv.x); d[1] = to_tf32(qv.y);
        d[2] = to_tf32(qv.z); d[3] = to_tf32(qv.w);
    }
    if (t < 64) { mrow[t] = -1e30f; lrow[t] = 0.f; }

    float oacc[4][4];
#pragma unroll
    for (int in = 0; in < 4; in++)
#pragma unroll
        for (int c = 0; c < 4; c++) oacc[in][c] = 0.f;

    int ntiles = blockIdx.x + 1;
    __syncthreads();

    for (int jt = 0; jt < ntiles; jt++) {
        int s0 = jt * 64;
        bool diag = (jt == ntiles - 1);

        for (int i = t; i < 64 * 16; i += 256) {
            int r = i >> 4, c4 = i & 15;
            size_t gb = ((size_t)(b * Tt + s0 + r)) * Dd + h * HD + c4 * 4;
            float4 kv = *(const float4*)(k + gb);
            float4 vv = *(const float4*)(v + gb);
            float* dk = Ks + r * ATP + c4 * 4;
            dk[0] = to_tf32(kv.x); dk[1] = to_tf32(kv.y);
            dk[2] = to_tf32(kv.z); dk[3] = to_tf32(kv.w);
            float* dv = Vs + r * ATP + c4 * 4;
            dv[0] = to_tf32(vv.x); dv[1] = to_tf32(vv.y);
            dv[2] = to_tf32(vv.z); dv[3] = to_tf32(vv.w);
        }
        __syncthreads();

        float sacc[4][4];
#pragma unroll
        for (int in = 0; in < 4; in++)
#pragma unroll
            for (int c = 0; c < 4; c++) sacc[in][c] = 0.f;
#pragma unroll
        for (int k8 = 0; k8 < 8; k8++) {
            int kk = k8 * 8;
            unsigned a0 = __float_as_uint(Qs[(m0 + g    ) * ATP + kk + tig    ]);
            unsigned a1 = __float_as_uint(Qs[(m0 + g + 8) * ATP + kk + tig    ]);
            unsigned a2 = __float_as_uint(Qs[(m0 + g    ) * ATP + kk + tig + 4]);
            unsigned a3 = __float_as_uint(Qs[(m0 + g + 8) * ATP + kk + tig + 4]);
#pragma unroll
            for (int in = 0; in < 4; in++) {
                unsigned b0 = __float_as_uint(Ks[(n0 + in * 8 + g) * ATP + kk + tig    ]);
                unsigned b1 = __float_as_uint(Ks[(n0 + in * 8 + g) * ATP + kk + tig + 4]);
                asm volatile(
                    "mma.sync.aligned.m16n8k8.row.col.f32.tf32.tf32.f32 "
                    "{%0,%1,%2,%3},{%4,%5,%6,%7},{%8,%9},{%0,%1,%2,%3};"
                    : "+f"(sacc[in][0]), "+f"(sacc[in][1]),
                      "+f"(sacc[in][2]), "+f"(sacc[in][3])
                    : "r"(a0), "r"(a1), "r"(a2), "r"(a3), "r"(b0), "r"(b1));
            }
        }

        int r0 = m0 + g, r1 = m0 + g + 8;
#pragma unroll
        for (int in = 0; in < 4; in++) {
            int c0 = n0 + in * 8 + 2 * tig, c1 = c0 + 1;
            sacc[in][0] *= 0.125f; sacc[in][1] *= 0.125f;
            sacc[in][2] *= 0.125f; sacc[in][3] *= 0.125f;
            if (diag) {
                if (c0 > r0) sacc[in][0] = -1e30f;
                if (c1 > r0) sacc[in][1] = -1e30f;
                if (c0 > r1) sacc[in][2] = -1e30f;
                if (c1 > r1) sacc[in][3] = -1e30f;
            }
        }

        float rmax0 = -1e30f, rmax1 = -1e30f;
#pragma unroll
        for (int in = 0; in < 4; in++) {
            rmax0 = fmaxf(rmax0, fmaxf(sacc[in][0], sacc[in][1]));
            rmax1 = fmaxf(rmax1, fmaxf(sacc[in][2], sacc[in][3]));
        }
        rmax0 = fmaxf(rmax0, __shfl_xor_sync(0xffffffffu, rmax0, 1));
        rmax0 = fmaxf(rmax0, __shfl_xor_sync(0xffffffffu, rmax0, 2));
        rmax1 = fmaxf(rmax1, __shfl_xor_sync(0xffffffffu, rmax1, 1));
        rmax1 = fmaxf(rmax1, __shfl_xor_sync(0xffffffffu, rmax1, 2));
        if (tig == 0) {
            pmax[nch * 64 + r0] = rmax0;
            pmax[nch * 64 + r1] = rmax1;
        }
        __syncthreads();

        if (t < 64) {
            float nm = fmaxf(mrow[t], fmaxf(pmax[t], pmax[64 + t]));
            cfac[t] = __expf(mrow[t] - nm);
            mrow[t] = nm;
        }
        __syncthreads();

        float nm0 = mrow[r0], nm1 = mrow[r1];
        float rs0 = 0.f, rs1 = 0.f;
#pragma unroll
        for (int in = 0; in < 4; in++) {
            int c0 = n0 + in * 8 + 2 * tig;
            float p0 = __expf(sacc[in][0] - nm0);
            float p1 = __expf(sacc[in][1] - nm0);
            float p2 = __expf(sacc[in][2] - nm1);
            float p3 = __expf(sacc[in][3] - nm1);
            rs0 += p0 + p1; rs1 += p2 + p3;
            Ps[r0 * ATP + c0    ] = to_tf32(p0);
            Ps[r0 * ATP + c0 + 1] = to_tf32(p1);
            Ps[r1 * ATP + c0    ] = to_tf32(p2);
            Ps[r1 * ATP + c0 + 1] = to_tf32(p3);
        }
        rs0 += __shfl_xor_sync(0xffffffffu, rs0, 1);
        rs0 += __shfl_xor_sync(0xffffffffu, rs0, 2);
        rs1 += __shfl_xor_sync(0xffffffffu, rs1, 1);
        rs1 += __shfl_xor_sync(0xffffffffu, rs1, 2);
        if (tig == 0) {
            psum[nch * 64 + r0] = rs0;
            psum[nch * 64 + r1] = rs1;
        }
        __syncthreads();

        if (t < 64) lrow[t] = lrow[t] * cfac[t] + psum[t] + psum[64 + t];

        float corr0 = cfac[r0], corr1 = cfac[r1];
#pragma unroll
        for (int in = 0; in < 4; in++) {
            oacc[in][0] *= corr0; oacc[in][1] *= corr0;
            oacc[in][2] *= corr1; oacc[in][3] *= corr1;
        }

#pragma unroll
        for (int k8 = 0; k8 < 8; k8++) {
            int kk = k8 * 8;
            unsigned a0 = __float_as_uint(Ps[(m0 + g    ) * ATP + kk + tig    ]);
            unsigned a1 = __float_as_uint(Ps[(m0 + g + 8) * ATP + kk + tig    ]);
            unsigned a2 = __float_as_uint(Ps[(m0 + g    ) * ATP + kk + tig + 4]);
            unsigned a3 = __float_as_uint(Ps[(m0 + g + 8) * ATP + kk + tig + 4]);
#pragma unroll
            for (int in = 0; in < 4; in++) {
                unsigned b0 = __float_as_uint(Vs[(kk + tig    ) * ATP + n0 + in * 8 + g]);
                unsigned b1 = __float_as_uint(Vs[(kk + tig + 4) * ATP + n0 + in * 8 + g]);
                asm volatile(
                    "mma.sync.aligned.m16n8k8.row.col.f32.tf32.tf32.f32 "
                    "{%0,%1,%2,%3},{%4,%5,%6,%7},{%8,%9},{%0,%1,%2,%3};"
                    : "+f"(oacc[in][0]), "+f"(oacc[in][1]),
                      "+f"(oacc[in][2]), "+f"(oacc[in][3])
                    : "r"(a0), "r"(a1), "r"(a2), "r"(a3), "r"(b0), "r"(b1));
            }
        }
        __syncthreads();
    }

    int r0 = m0 + g, r1 = m0 + g + 8;
    float inv0 = 1.f / lrow[r0];
    float inv1 = 1.f / lrow[r1];
#pragma unroll
    for (int in = 0; in < 4; in++) {
        int c0 = n0 + in * 8 + 2 * tig;
        float2 o0, o1;
        o0.x = oacc[in][0] * inv0; o0.y = oacc[in][1] * inv0;
        o1.x = oacc[in][2] * inv1; o1.y = oacc[in][3] * inv1;
        *(float2*)(y + ((size_t)(b * Tt + q0 + r0)) * Dd + h * HD + c0) = o0;
        *(float2*)(y + ((size_t)(b * Tt + q0 + r1)) * Dd + h * HD + c0) = o1;
    }
}

// ---------------- residual + LayerNorm (192 thr, float4, optional tf32 copy) ----------------
template<int NIN>
__device__ __forceinline__ void ln_core(
    const float* a, const float* b, const float* c2, const float* d2,
    const float* __restrict__ g, const float* __restrict__ be,
    float* out, float* out_t) {
    __shared__ float wred[6];
    __shared__ float stat;
    int r = blockIdx.x;
    int t = threadIdx.x;
    int lane = t & 31, wrp = t >> 5;

    float4 v = ((const float4*)(a + (size_t)r * Dd))[t];
    {
        float4 u = ((const float4*)(b + (size_t)r * Dd))[t];
        v.x += u.x; v.y += u.y; v.z += u.z; v.w += u.w;
    }
    if (NIN == 4) {
        float4 u = ((const float4*)(c2 + (size_t)r * Dd))[t];
        v.x += u.x; v.y += u.y; v.z += u.z; v.w += u.w;
        float4 w = ((const float4*)(d2 + (size_t)r * Dd))[t];
        v.x += w.x; v.y += w.y; v.z += w.z; v.w += w.w;
    }

    float s = (v.x + v.y) + (v.z + v.w);
#pragma unroll
    for (int o = 16; o > 0; o >>= 1) s += __shfl_xor_sync(0xffffffffu, s, o);
    if (lane == 0) wred[wrp] = s;
    __syncthreads();
    if (t == 0) {
        float tot = ((wred[0] + wred[1]) + (wred[2] + wred[3])) + (wred[4] + wred[5]);
        stat = tot / (float)Dd;
    }
    __syncthreads();
    float mu = stat;

    float dx = v.x - mu, dy = v.y - mu, dz = v.z - mu, dw = v.w - mu;
    float s2 = (dx * dx + dy * dy) + (dz * dz + dw * dw);
#pragma unroll
    for (int o = 16; o > 0; o >>= 1) s2 += __shfl_xor_sync(0xffffffffu, s2, o);
    __syncthreads();
    if (lane == 0) wred[wrp] = s2;
    __syncthreads();
    if (t == 0) {
        float tot = ((wred[0] + wred[1]) + (wred[2] + wred[3])) + (wred[4] + wred[5]);
        stat = rsqrtf(tot / (float)Dd + 1e-5f);
    }
    __syncthreads();
    float rstd = stat;

    float4 gv = ((const float4*)g)[t];
    float4 bv = ((const float4*)be)[t];
    float4 o4;
    o4.x = dx * rstd * gv.x + bv.x;
    o4.y = dy * rstd * gv.y + bv.y;
    o4.z = dz * rstd * gv.z + bv.z;
    o4.w = dw * rstd * gv.w + bv.w;
    ((float4*)(out + (size_t)r * Dd))[t] = o4;
    float4 t4;
    t4.x = to_tf32(o4.x); t4.y = to_tf32(o4.y);
    t4.z = to_tf32(o4.z); t4.w = to_tf32(o4.w);
    ((float4*)(out_t + (size_t)r * Dd))[t] = t4;
}

__global__ __launch_bounds__(192)
void ln_res_kernel(const float* __restrict__ a, const float* __restrict__ b,
                   const float* __restrict__ g, const float* __restrict__ be,
                   float* __restrict__ out, float* __restrict__ out_t) {
    ln_core<2>(a, b, nullptr, nullptr, g, be, out, out_t);
}

__global__ __launch_bounds__(192)
void ln_res4_kernel(const float* __restrict__ a, const float* __restrict__ b,
                    const float* __restrict__ c2, const float* __restrict__ d2,
                    const float* __restrict__ g, const float* __restrict__ be,
                    float* __restrict__ out, float* __restrict__ out_t) {
    ln_core<4>(a, b, c2, d2, g, be, out, out_t);
}

// ---------------- per-row cross-entropy (float4, alignment-peeled) ----------------
__global__ __launch_bounds__(256)
void rowloss_kernel(const float* __restrict__ logits, const int* __restrict__ tgt,
                    float* __restrict__ rl) {
    __shared__ float sm[256], sl[256];
    int r = blockIdx.x;
    int t = threadIdx.x;
    const float* lg = logits + (size_t)r * Vv;

    float m = -1e30f, l = 0.f;
    auto accum = [&](float x) {
        if (x > m) { l = l * __expf(m - x) + 1.f; m = x; }
        else       { l += __expf(x - m); }
    };

    int skip = (4 - (r & 3)) & 3;
    if (t < skip) accum(lg[t]);
    const float4* lg4 = (const float4*)(lg + skip);
    int n4 = (Vv - skip) >> 2;
    for (int i = t; i < n4; i += 256) {
        float4 x4 = lg4[i];
        accum(x4.x); accum(x4.y); accum(x4.z); accum(x4.w);
    }
    int tail = skip + n4 * 4 + t;
    if (tail < Vv) accum(lg[tail]);

    sm[t] = m; sl[t] = l; __syncthreads();
    for (int o = 128; o > 0; o >>= 1) {
        if (t < o) {
            float m1 = sm[t], m2 = sm[t + o];
            float M = fmaxf(m1, m2);
            sl[t] = sl[t] * __expf(m1 - M) + sl[t + o] * __expf(m2 - M);
            sm[t] = M;
        }
        __syncthreads();
    }
    if (t == 0)
        rl[r] = (sm[0] + logf(sl[0])) - lg[tgt[r]];
}

__global__ __launch_bounds__(256)
void meanloss_kernel(const float* __restrict__ rl, float* __restrict__ out) {
    __shared__ float red[256];
    int t = threadIdx.x;
    float s = 0.f;
    for (int i = t; i < BT; i += 256) s += rl[i];
    red[t] = s; __syncthreads();
    for (int o = 128; o > 0; o >>= 1) { if (t < o) red[t] += red[t + o]; __syncthreads(); }
    if (t == 0) out[0] = red[0] / (float)BT;
}

// ---------------- launch ----------------
extern "C" void kernel_launch(void* const* d_in, const int* in_sizes, int n_in,
                              void* d_out, int out_size) {
    const int*   idx    = (const int*)  d_in[0];
    const int*   tgt    = (const int*)  d_in[1];
    const float* tok    = (const float*)d_in[2];
    const float* pos    = (const float*)d_in[3];
    const float* Wq     = (const float*)d_in[4];
    const float* Wk     = (const float*)d_in[5];
    const float* Wv     = (const float*)d_in[6];
    const float* ln1g   = (const float*)d_in[7];
    const float* ln1b   = (const float*)d_in[8];
    const float* W1     = (const float*)d_in[9];
    const float* b1     = (const float*)d_in[10];
    const float* W2     = (const float*)d_in[11];
    const float* b2     = (const float*)d_in[12];
    const float* ln2g   = (const float*)d_in[13];
    const float* ln2b   = (const float*)d_in[14];
    const float* headw  = (const float*)d_in[15];
    const float* headb  = (const float*)d_in[16];
    float* out = (float*)d_out;

    float *x, *xt, *x2, *x2t, *q, *k, *v, *y, *ff1, *rl, *wpad;
    float *wqt, *wkt, *wvt, *w1t, *w2t;
    cudaGetSymbolAddress((void**)&x,    g_x);
    cudaGetSymbolAddress((void**)&xt,   g_xt);
    cudaGetSymbolAddress((void**)&x2,   g_x2);
    cudaGetSymbolAddress((void**)&x2t,  g_x2t);
    cudaGetSymbolAddress((void**)&q,    g_q);
    cudaGetSymbolAddress((void**)&k,    g_k);
    cudaGetSymbolAddress((void**)&v,    g_v);
    cudaGetSymbolAddress((void**)&y,    g_y);
    cudaGetSymbolAddress((void**)&ff1,  g_ff1);
    cudaGetSymbolAddress((void**)&rl,   g_rl);
    cudaGetSymbolAddress((void**)&wpad, g_wpad);
    cudaGetSymbolAddress((void**)&wqt,  g_wqt);
    cudaGetSymbolAddress((void**)&wkt,  g_wkt);
    cudaGetSymbolAddress((void**)&wvt,  g_wvt);
    cudaGetSymbolAddress((void**)&w1t,  g_w1t);
    cudaGetSymbolAddress((void**)&w2t,  g_w2t);

    cudaFuncSetAttribute(attn_kernel,
                         cudaFuncAttributeMaxDynamicSharedMemorySize, ATTN_SMEM);

    // pre-convert weights to tf32 (one pass, independent of layer stack)
    const int nQ = Ll * Dd * Dd / 4, nF = Ll * Dd * FF / 4;
    cvtw_kernel<<<(nQ + 255) / 256, 256>>>(Wq, wqt, nQ);
    cvtw_kernel<<<(nQ + 255) / 256, 256>>>(Wk, wkt, nQ);
    cvtw_kernel<<<(nQ + 255) / 256, 256>>>(Wv, wvt, nQ);
    cvtw_kernel<<<(nF + 255) / 256, 256>>>(W1, w1t, nF);
    cvtw_kernel<<<(nF + 255) / 256, 256>>>(W2, w2t, nF);
    padw_kernel<<<Dd, 256>>>(headw, wpad);
    embed_kernel<<<BT, 256>>>(idx, tok, pos, x, xt);

    dim3 gQKV(18, BT / 128);
    dim3 gF(FF / 128, BT / 128);             // 24 x 32
    dim3 gF2(18, BT / 128);                  // 3 K-parts x 6 col-tiles
    dim3 gVs(BT / 128, VP / 128);            // 32 x 393

    for (int l = 0; l < Ll; l++) {
        const float* wq = wqt + (size_t)l * Dd * Dd;
        const float* wk = wkt + (size_t)l * Dd * Dd;
        const float* wv = wvt + (size_t)l * Dd * Dd;
        const float* w1 = w1t + (size_t)l * Dd * FF;
        const float* w2 = w2t + (size_t)l * FF * Dd;

        qkv_kernel<<<gQKV, 256>>>(xt, wq, wk, wv, q, k, v);

        attn_kernel<<<dim3(Tt / 64, Hh, Bb), 256, ATTN_SMEM>>>(q, k, v, y);

        ln_res_kernel<<<BT, 192>>>(y, x, ln1g + l * Dd, ln1b + l * Dd, x2, x2t);

        tgemm_kernel<3><<<gF, 256>>>(x2t, w1, b1 + (size_t)l * FF, ff1, FF, Dd, FF);

        ffn2_kernel<<<gF2, 256>>>(ff1, w2, b2 + (size_t)l * Dd, y, q, k);

        ln_res4_kernel<<<BT, 192>>>(y, q, k, x2, ln2g + l * Dd, ln2b + l * Dd, x, xt);
    }

    tgemm_swap_kernel<<<gVs, 256>>>(xt, wpad, headb, out, Vv, Dd, VP);

    rowloss_kernel<<<BT, 256>>>(out, tgt, rl);
    meanloss_kernel<<<1, 256>>>(rl, out + (size_t)BT * Vv);
}